// round 1
// baseline (speedup 1.0000x reference)
#include <cuda_runtime.h>
#include <cstdint>

#define D 256
#define DFF 512
#define NMAX 50000

// -------- scratch (static device globals: no allocation allowed) ----------
__device__ float g_agg[(size_t)NMAX * D];   // agg, later reused for pre-LN2
__device__ float g_h[(size_t)NMAX * D];     // h_pre -> h (in-place LN)
__device__ float g_t[(size_t)NMAX * DFF];   // relu(h@W1+b1)
__device__ int   g_is64;

// -------------------------- zero fill -------------------------------------
__global__ void zero_kernel(float* __restrict__ p, int n4) {
    int i = blockIdx.x * blockDim.x + threadIdx.x;
    if (i < n4) ((float4*)p)[i] = make_float4(0.f, 0.f, 0.f, 0.f);
}

// ---------------- edge_index dtype detection (int32 vs int64) -------------
// If int64: odd 32-bit words are high words of small nonneg indices -> all 0.
__global__ void detect_kernel(const int* __restrict__ ei, int twoE) {
    int nz = 0;
    int lim = twoE * 2;           // if int64 there are 2*twoE words; if int32 only twoE
    if (lim > 256) lim = 256;
    for (int i = 1; i < lim; i += 2) nz |= ei[i];
    g_is64 = (nz == 0) ? 1 : 0;
}

// ------------------------- edge scatter-add -------------------------------
// one warp per edge; each lane does 2x float4 load + 2x red.global.add.v4.f32
__global__ void scatter_kernel(const int* __restrict__ ei, int E,
                               const float* __restrict__ x,
                               float* __restrict__ agg) {
    int warp = (blockIdx.x * blockDim.x + threadIdx.x) >> 5;
    int lane = threadIdx.x & 31;
    if (warp >= E) return;
    int is64 = g_is64;
    int s, d;
    if (is64) { s = ei[2 * warp]; d = ei[2 * (E + warp)]; }
    else      { s = ei[warp];     d = ei[E + warp]; }
    const float4* xs = (const float4*)(x + (size_t)s * D);
    float4* ad = (float4*)(agg + (size_t)d * D);
#pragma unroll
    for (int j = 0; j < 2; ++j) {
        float4 v = xs[lane + 32 * j];
        float* addr = (float*)&ad[lane + 32 * j];
        asm volatile("red.global.add.v4.f32 [%0], {%1,%2,%3,%4};"
                     :: "l"(addr), "f"(v.x), "f"(v.y), "f"(v.z), "f"(v.w)
                     : "memory");
    }
}

// ------------------------- fused tiled GEMM -------------------------------
// C[M,N] = A0[M,K0]@B0[K0,N] (+ A1[M,K1]@B1[K1,N]) + bias (+ resid) (+relu)
// BM=128, BN=128, BK=16, 256 threads, 8x8 per thread.
#define BM 128
#define BN 128
#define BK 16

template <bool RELU>
__global__ __launch_bounds__(256, 2)
void gemm_fused(const float* __restrict__ A0, const float* __restrict__ B0, int K0,
                const float* __restrict__ A1, const float* __restrict__ B1, int K1,
                const float* __restrict__ bias,
                const float* __restrict__ resid,
                float* __restrict__ C, int M, int N) {
    __shared__ float As[BK][BM];
    __shared__ float Bs[BK][BN];

    const int tid = threadIdx.x;
    const int tx = tid & 15;          // 0..15 -> N direction
    const int ty = tid >> 4;          // 0..15 -> M direction
    const int row0 = blockIdx.x * BM;
    const int col0 = blockIdx.y * BN;

    float acc[8][8];
#pragma unroll
    for (int i = 0; i < 8; ++i)
#pragma unroll
        for (int j = 0; j < 8; ++j) acc[i][j] = 0.f;

    for (int phase = 0; phase < 2; ++phase) {
        const float* A = phase ? A1 : A0;
        const float* B = phase ? B1 : B0;
        const int K = phase ? K1 : K0;
        if (A == nullptr) continue;

        for (int kk = 0; kk < K; kk += BK) {
            __syncthreads();
            // load A tile (BM x BK), store transposed As[k][m]
#pragma unroll
            for (int r = 0; r < 2; ++r) {
                int a_row = (tid >> 2) + r * 64;
                int a_col = (tid & 3) * 4;
                int grow = row0 + a_row;
                float4 v = make_float4(0.f, 0.f, 0.f, 0.f);
                if (grow < M)
                    v = *(const float4*)&A[(size_t)grow * K + kk + a_col];
                As[a_col + 0][a_row] = v.x;
                As[a_col + 1][a_row] = v.y;
                As[a_col + 2][a_row] = v.z;
                As[a_col + 3][a_row] = v.w;
            }
            // load B tile (BK x BN)
#pragma unroll
            for (int r = 0; r < 2; ++r) {
                int b_row = (tid >> 5) + r * 8;
                int b_col = (tid & 31) * 4;
                *(float4*)&Bs[b_row][b_col] =
                    *(const float4*)&B[(size_t)(kk + b_row) * N + col0 + b_col];
            }
            __syncthreads();
#pragma unroll
            for (int k = 0; k < BK; ++k) {
                float a[8], b[8];
                *(float4*)&a[0] = *(const float4*)&As[k][ty * 8];
                *(float4*)&a[4] = *(const float4*)&As[k][ty * 8 + 4];
                *(float4*)&b[0] = *(const float4*)&Bs[k][tx * 8];
                *(float4*)&b[4] = *(const float4*)&Bs[k][tx * 8 + 4];
#pragma unroll
                for (int i = 0; i < 8; ++i)
#pragma unroll
                    for (int j = 0; j < 8; ++j)
                        acc[i][j] += a[i] * b[j];
            }
        }
    }

    // epilogue
#pragma unroll
    for (int i = 0; i < 8; ++i) {
        int r = row0 + ty * 8 + i;
        if (r >= M) continue;
#pragma unroll
        for (int j = 0; j < 8; j += 4) {
            int c = col0 + tx * 8 + j;
            float4 o;
            o.x = acc[i][j + 0] + bias[c + 0];
            o.y = acc[i][j + 1] + bias[c + 1];
            o.z = acc[i][j + 2] + bias[c + 2];
            o.w = acc[i][j + 3] + bias[c + 3];
            if (resid != nullptr) {
                float4 rv = *(const float4*)&resid[(size_t)r * N + c];
                o.x += rv.x; o.y += rv.y; o.z += rv.z; o.w += rv.w;
            }
            if (RELU) {
                o.x = fmaxf(o.x, 0.f); o.y = fmaxf(o.y, 0.f);
                o.z = fmaxf(o.z, 0.f); o.w = fmaxf(o.w, 0.f);
            }
            *(float4*)&C[(size_t)r * N + c] = o;
        }
    }
}

// --------------------------- layernorm ------------------------------------
// one warp per row (256 cols), 8 rows per 256-thread block
__global__ void ln_kernel(const float* __restrict__ in,
                          const float* __restrict__ gamma,
                          const float* __restrict__ beta,
                          float* __restrict__ out, int Nrows) {
    int row = blockIdx.x * 8 + (threadIdx.x >> 5);
    int lane = threadIdx.x & 31;
    if (row >= Nrows) return;
    const float4* p = (const float4*)(in + (size_t)row * D);
    float4 v0 = p[lane];
    float4 v1 = p[lane + 32];
    float s  = v0.x + v0.y + v0.z + v0.w + v1.x + v1.y + v1.z + v1.w;
    float sq = v0.x * v0.x + v0.y * v0.y + v0.z * v0.z + v0.w * v0.w +
               v1.x * v1.x + v1.y * v1.y + v1.z * v1.z + v1.w * v1.w;
#pragma unroll
    for (int o = 16; o; o >>= 1) {
        s  += __shfl_xor_sync(0xFFFFFFFFu, s, o);
        sq += __shfl_xor_sync(0xFFFFFFFFu, sq, o);
    }
    float mean = s * (1.0f / D);
    float var  = sq * (1.0f / D) - mean * mean;
    float inv  = rsqrtf(var + 1e-5f);
    const float4* gp = (const float4*)gamma;
    const float4* bp = (const float4*)beta;
    float4* op = (float4*)(out + (size_t)row * D);
#pragma unroll
    for (int j = 0; j < 2; ++j) {
        float4 v = j ? v1 : v0;
        float4 g = gp[lane + 32 * j];
        float4 b = bp[lane + 32 * j];
        float4 o;
        o.x = (v.x - mean) * inv * g.x + b.x;
        o.y = (v.y - mean) * inv * g.y + b.y;
        o.z = (v.z - mean) * inv * g.z + b.z;
        o.w = (v.w - mean) * inv * g.w + b.w;
        op[lane + 32 * j] = o;
    }
}

// ------------------------------ launch ------------------------------------
extern "C" void kernel_launch(void* const* d_in, const int* in_sizes, int n_in,
                              void* d_out, int out_size) {
    const float* x      = (const float*)d_in[0];
    const int*   ei     = (const int*)d_in[1];
    const float* W_nbr  = (const float*)d_in[2];
    const float* W_root = (const float*)d_in[3];
    const float* b_gnn  = (const float*)d_in[4];
    const float* W1     = (const float*)d_in[5];
    const float* b1     = (const float*)d_in[6];
    const float* W2     = (const float*)d_in[7];
    const float* b2     = (const float*)d_in[8];
    const float* g1     = (const float*)d_in[9];
    const float* be1    = (const float*)d_in[10];
    const float* g2     = (const float*)d_in[11];
    const float* be2    = (const float*)d_in[12];
    float* out = (float*)d_out;

    const int M = in_sizes[0] / D;
    const int E = in_sizes[1] / 2;

    float *agg, *h, *t;
    cudaGetSymbolAddress((void**)&agg, g_agg);
    cudaGetSymbolAddress((void**)&h,   g_h);
    cudaGetSymbolAddress((void**)&t,   g_t);

    // 1. zero agg
    int n4 = M * D / 4;
    zero_kernel<<<(n4 + 255) / 256, 256>>>(agg, n4);

    // 2. detect edge_index dtype, 3. scatter-add
    detect_kernel<<<1, 1>>>(ei, 2 * E);
    scatter_kernel<<<(E + 7) / 8, 256>>>(ei, E, x, agg);

    // 4. x2 = agg@W_nbr + x@W_root + b_gnn; h_pre = x + x2
    dim3 grid1((M + BM - 1) / BM, D / BN);
    gemm_fused<false><<<grid1, 256>>>(agg, W_nbr, D, x, W_root, D,
                                      b_gnn, x, h, M, D);
    // 5. h = LN(h_pre)
    ln_kernel<<<(M + 7) / 8, 256>>>(h, g1, be1, h, M);

    // 6. t = relu(h@W1 + b1)
    dim3 grid2((M + BM - 1) / BM, DFF / BN);
    gemm_fused<true><<<grid2, 256>>>(h, W1, D, nullptr, nullptr, 0,
                                     b1, nullptr, t, M, DFF);

    // 7. pre2 = h + t@W2 + b2   (reuse agg buffer)
    dim3 grid3((M + BM - 1) / BM, D / BN);
    gemm_fused<false><<<grid3, 256>>>(t, W2, DFF, nullptr, nullptr, 0,
                                      b2, h, agg, M, D);

    // 8. out = LN(pre2)
    ln_kernel<<<(M + 7) / 8, 256>>>(agg, g2, be2, out, M);
}

// round 3
// speedup vs baseline: 1.5919x; 1.5919x over previous
#include <cuda_runtime.h>
#include <cuda_bf16.h>
#include <cstdint>

#define HD 256
#define HF 512
#define NMAX 50000

// ------------------------- scratch (device globals) ------------------------
__device__ float g_agg[(size_t)NMAX * HD];
__device__ float g_h[(size_t)NMAX * HD];
__device__ __nv_bfloat16 g_x_h[(size_t)NMAX * HD];
__device__ __nv_bfloat16 g_x_l[(size_t)NMAX * HD];
__device__ __nv_bfloat16 g_ag_h[(size_t)NMAX * HD];
__device__ __nv_bfloat16 g_ag_l[(size_t)NMAX * HD];
__device__ __nv_bfloat16 g_h_h[(size_t)NMAX * HD];
__device__ __nv_bfloat16 g_h_l[(size_t)NMAX * HD];
__device__ __nv_bfloat16 g_t_h[(size_t)NMAX * HF];
__device__ __nv_bfloat16 g_t_l[(size_t)NMAX * HF];
__device__ __nv_bfloat16 g_wn_h[HD * HD], g_wn_l[HD * HD];
__device__ __nv_bfloat16 g_wr_h[HD * HD], g_wr_l[HD * HD];
__device__ __nv_bfloat16 g_w1_h[HD * HF], g_w1_l[HD * HF];
__device__ __nv_bfloat16 g_w2_h[HD * HF], g_w2_l[HD * HF];
__device__ int g_is64;

// ----------------------------- helpers -------------------------------------
__device__ __forceinline__ uint32_t smem_u32(const void* p) {
    uint32_t a;
    asm("{ .reg .u64 t; cvta.to.shared.u64 t, %1; cvt.u32.u64 %0, t; }" : "=r"(a) : "l"(p));
    return a;
}
__device__ __forceinline__ void ldsm_x4(uint32_t* r, uint32_t addr) {
    asm volatile("ldmatrix.sync.aligned.m8n8.x4.shared.b16 {%0,%1,%2,%3}, [%4];"
                 : "=r"(r[0]), "=r"(r[1]), "=r"(r[2]), "=r"(r[3]) : "r"(addr));
}
__device__ __forceinline__ void ldsm_x2(uint32_t* r, uint32_t addr) {
    asm volatile("ldmatrix.sync.aligned.m8n8.x2.shared.b16 {%0,%1}, [%2];"
                 : "=r"(r[0]), "=r"(r[1]) : "r"(addr));
}
__device__ __forceinline__ void mma_bf16(float* d, const uint32_t* a, const uint32_t* b) {
    asm volatile(
        "mma.sync.aligned.m16n8k16.row.col.f32.bf16.bf16.f32 "
        "{%0,%1,%2,%3}, {%4,%5,%6,%7}, {%8,%9}, {%0,%1,%2,%3};"
        : "+f"(d[0]), "+f"(d[1]), "+f"(d[2]), "+f"(d[3])
        : "r"(a[0]), "r"(a[1]), "r"(a[2]), "r"(a[3]), "r"(b[0]), "r"(b[1]));
}
__device__ __forceinline__ void cp_async16(uint32_t dst, const void* src, int szr) {
    asm volatile("cp.async.cg.shared.global [%0], [%1], 16, %2;"
                 :: "r"(dst), "l"(src), "r"(szr) : "memory");
}
#define CP_COMMIT() asm volatile("cp.async.commit_group;" ::: "memory")
#define CP_WAIT1()  asm volatile("cp.async.wait_group 1;" ::: "memory")
#define CP_WAIT0()  asm volatile("cp.async.wait_group 0;" ::: "memory")

__device__ __forceinline__ uint32_t pack2bf(float a, float b, uint32_t& lopack) {
    __nv_bfloat16 ha = __float2bfloat16(a), hb = __float2bfloat16(b);
    float la = a - __bfloat162float(ha), lb = b - __bfloat162float(hb);
    __nv_bfloat16 lA = __float2bfloat16(la), lB = __float2bfloat16(lb);
    lopack = (uint32_t)__bfloat16_as_ushort(lA) | ((uint32_t)__bfloat16_as_ushort(lB) << 16);
    return (uint32_t)__bfloat16_as_ushort(ha) | ((uint32_t)__bfloat16_as_ushort(hb) << 16);
}

// --------------------------- small kernels ---------------------------------
__global__ void zero_kernel(float* __restrict__ p, int n4) {
    int i = blockIdx.x * blockDim.x + threadIdx.x;
    if (i < n4) ((float4*)p)[i] = make_float4(0.f, 0.f, 0.f, 0.f);
}

__global__ void detect_kernel(const int* __restrict__ ei, int twoE) {
    int nz = 0;
    int lim = twoE * 2;
    if (lim > 256) lim = 256;
    for (int i = 1; i < lim; i += 2) nz |= ei[i];
    g_is64 = (nz == 0) ? 1 : 0;
}

__global__ void scatter_kernel(const int* __restrict__ ei, int E,
                               const float* __restrict__ x,
                               float* __restrict__ agg) {
    int warp = (blockIdx.x * blockDim.x + threadIdx.x) >> 5;
    int lane = threadIdx.x & 31;
    if (warp >= E) return;
    int s, d;
    if (g_is64) { s = ei[2 * warp]; d = ei[2 * (E + warp)]; }
    else        { s = ei[warp];     d = ei[E + warp]; }
    const float4* xs = (const float4*)(x + (size_t)s * HD);
    float4* ad = (float4*)(agg + (size_t)d * HD);
#pragma unroll
    for (int j = 0; j < 2; ++j) {
        float4 v = xs[lane + 32 * j];
        float* addr = (float*)&ad[lane + 32 * j];
        asm volatile("red.global.add.v4.f32 [%0], {%1,%2,%3,%4};"
                     :: "l"(addr), "f"(v.x), "f"(v.y), "f"(v.z), "f"(v.w) : "memory");
    }
}

__global__ void split_kernel(const float* __restrict__ in,
                             __nv_bfloat16* __restrict__ oh,
                             __nv_bfloat16* __restrict__ ol, int n4) {
    int i = blockIdx.x * blockDim.x + threadIdx.x;
    if (i >= n4) return;
    float4 v = ((const float4*)in)[i];
    uint32_t l0, l1;
    uint32_t h0 = pack2bf(v.x, v.y, l0);
    uint32_t h1 = pack2bf(v.z, v.w, l1);
    ((uint2*)oh)[i] = make_uint2(h0, h1);
    ((uint2*)ol)[i] = make_uint2(l0, l1);
}

// W [K,N] -> out [N,K] hi/lo
__global__ void tsplit_kernel(const float* __restrict__ W,
                              __nv_bfloat16* __restrict__ oh,
                              __nv_bfloat16* __restrict__ ol, int K, int N) {
    int idx = blockIdx.x * blockDim.x + threadIdx.x;
    if (idx >= K * N) return;
    int n = idx / K, k = idx - n * K;
    float v = W[(size_t)k * N + n];
    __nv_bfloat16 h = __float2bfloat16(v);
    oh[idx] = h;
    ol[idx] = __float2bfloat16(v - __bfloat162float(h));
}

// ----------------------- bf16-split mma.sync GEMM --------------------------
// BM=64, BN=256, BK=32, 256 threads, 3-stage cp.async pipeline.
// smem stage: A (128 rows hi|lo x 80B) = 10240B, B (512 rows hi|lo x 80B) = 40960B
#define STAGE_BYTES 51200
#define SMEM_TOTAL  (3 * STAGE_BYTES)

__device__ __forceinline__ void load_stage(
    uint32_t sa, int tid, int row0, int col0,
    const __nv_bfloat16* Ah, const __nv_bfloat16* Al,
    const __nv_bfloat16* Bh, const __nv_bfloat16* Bl,
    int K, int kc, int M) {
#pragma unroll
    for (int j = 0; j < 2; ++j) {   // A: 512 chunks of 16B
        int id = tid + j * 256;
        int r = id >> 2, c = id & 3;
        int row = row0 + (r & 63);
        int szr = (row < M) ? 16 : 0;
        size_t roff = (row < M) ? (size_t)row : 0;
        const __nv_bfloat16* src = (r < 64 ? Ah : Al) + roff * K + kc + c * 8;
        cp_async16(sa + r * 80 + c * 16, src, szr);
    }
    uint32_t sb = sa + 10240;
#pragma unroll
    for (int j = 0; j < 8; ++j) {   // B: 2048 chunks
        int id = tid + j * 256;
        int r = id >> 2, c = id & 3;
        int n = col0 + (r & 255);
        const __nv_bfloat16* src = (r < 256 ? Bh : Bl) + (size_t)n * K + kc + c * 8;
        cp_async16(sb + r * 80 + c * 16, src, 16);
    }
}

// MODE 0: C = A@B(+A1@B1) + bias + resid -> LN(gamma,beta) -> outf (+opt hi/lo)
// MODE 1: C = relu(A@B + bias) -> hi/lo split only (stride HF)
template <int MODE>
__global__ void __launch_bounds__(256)
gemm_mma(const __nv_bfloat16* __restrict__ A0h, const __nv_bfloat16* __restrict__ A0l,
         const __nv_bfloat16* __restrict__ B0h, const __nv_bfloat16* __restrict__ B0l, int K0,
         const __nv_bfloat16* __restrict__ A1h, const __nv_bfloat16* __restrict__ A1l,
         const __nv_bfloat16* __restrict__ B1h, const __nv_bfloat16* __restrict__ B1l, int K1,
         const float* __restrict__ bias, const float* __restrict__ resid,
         const float* __restrict__ gamma, const float* __restrict__ beta,
         float* __restrict__ outf, __nv_bfloat16* __restrict__ outh,
         __nv_bfloat16* __restrict__ outl, int M) {
    extern __shared__ char smem[];
    const uint32_t sb0 = smem_u32(smem);
    const int tid = threadIdx.x;
    const int lane = tid & 31;
    const int warp = tid >> 5;
    const int warpM = warp >> 2;     // 0..1
    const int warpN = warp & 3;      // 0..3
    const int row0 = blockIdx.x * 64;
    const int col0 = blockIdx.y * 256;

    float acc[2][8][4];
#pragma unroll
    for (int i = 0; i < 2; ++i)
#pragma unroll
        for (int j = 0; j < 8; ++j)
#pragma unroll
            for (int k = 0; k < 4; ++k) acc[i][j][k] = 0.f;

    const int S = (K0 + K1) >> 5;

    // per-lane ldmatrix offsets (80B row stride -> conflict-free)
    const uint32_t aoff = (uint32_t)((warpM * 32 + (lane & 7) + ((lane >> 3) & 1) * 8) * 80
                                     + (lane >> 4) * 16);
    const uint32_t boff = (uint32_t)((warpN * 64 + (lane & 7)) * 80 + ((lane >> 3) & 1) * 16);

#define RESOLVE(IT, AH, AL, BH, BL, KK, KC)                                        \
    { int kt = (IT) * 32;                                                          \
      if (kt < K0) { AH = A0h; AL = A0l; BH = B0h; BL = B0l; KK = K0; KC = kt; }   \
      else         { AH = A1h; AL = A1l; BH = B1h; BL = B1l; KK = K1; KC = kt - K0; } }

    // prologue: stages 0,1
    {
        const __nv_bfloat16 *Ah, *Al, *Bh, *Bl; int KK, KC;
        RESOLVE(0, Ah, Al, Bh, Bl, KK, KC);
        load_stage(sb0, tid, row0, col0, Ah, Al, Bh, Bl, KK, KC, M);
        CP_COMMIT();
        if (S > 1) {
            RESOLVE(1, Ah, Al, Bh, Bl, KK, KC);
            load_stage(sb0 + STAGE_BYTES, tid, row0, col0, Ah, Al, Bh, Bl, KK, KC, M);
        }
        CP_COMMIT();
    }

    int stage = 0;
    for (int it = 0; it < S; ++it) {
        CP_WAIT1();
        __syncthreads();
        // prefetch stage it+2
        if (it + 2 < S) {
            int s2 = stage + 2; if (s2 >= 3) s2 -= 3;
            const __nv_bfloat16 *Ah, *Al, *Bh, *Bl; int KK, KC;
            RESOLVE(it + 2, Ah, Al, Bh, Bl, KK, KC);
            load_stage(sb0 + s2 * STAGE_BYTES, tid, row0, col0, Ah, Al, Bh, Bl, KK, KC, M);
        }
        CP_COMMIT();

        const uint32_t sa = sb0 + stage * STAGE_BYTES;
        const uint32_t sbB = sa + 10240;
#pragma unroll
        for (int ks = 0; ks < 2; ++ks) {
            uint32_t ah[2][4], al[2][4];
#pragma unroll
            for (int tm = 0; tm < 2; ++tm) {
                uint32_t base = sa + aoff + tm * 1280 + ks * 32;
                ldsm_x4(ah[tm], base);
                ldsm_x4(al[tm], base + 5120);
            }
#pragma unroll
            for (int tn = 0; tn < 8; ++tn) {
                uint32_t bh[2], bl[2];
                uint32_t ba = sbB + boff + tn * 640 + ks * 32;
                ldsm_x2(bh, ba);
                ldsm_x2(bl, ba + 20480);
#pragma unroll
                for (int tm = 0; tm < 2; ++tm) {
                    mma_bf16(acc[tm][tn], ah[tm], bh);
                    mma_bf16(acc[tm][tn], al[tm], bh);
                    mma_bf16(acc[tm][tn], ah[tm], bl);
                }
            }
        }
        ++stage; if (stage == 3) stage = 0;
    }

    CP_WAIT0();
    __syncthreads();

    // ---------------------------- epilogue ---------------------------------
    float* rsum  = (float*)smem;        // 64
    float* rsq   = rsum + 64;           // 64
    float* sbias = rsq + 64;            // 256
    float* sgam  = sbias + 256;
    float* sbet  = sgam + 256;
    if (MODE == 0 && tid < 64) { rsum[tid] = 0.f; rsq[tid] = 0.f; }
    sbias[tid] = bias[col0 + tid];
    if (MODE == 0) { sgam[tid] = gamma[tid]; sbet[tid] = beta[tid]; }
    __syncthreads();

    const int qrow = lane >> 2;
    const int qc = (lane & 3) * 2;

    float vsum[4], vsq[4];
#pragma unroll
    for (int k = 0; k < 4; ++k) { vsum[k] = 0.f; vsq[k] = 0.f; }

#pragma unroll
    for (int tm = 0; tm < 2; ++tm) {
#pragma unroll
        for (int rh = 0; rh < 2; ++rh) {
            int rloc = warpM * 32 + tm * 16 + rh * 8 + qrow;
            int rg = row0 + rloc;
            bool v = rg < M;
#pragma unroll
            for (int tn = 0; tn < 8; ++tn) {
                int c = warpN * 64 + tn * 8 + qc;
                float a0 = acc[tm][tn][rh * 2 + 0] + sbias[c];
                float a1 = acc[tm][tn][rh * 2 + 1] + sbias[c + 1];
                if (MODE == 0) {
                    if (v) {
                        float2 q = *(const float2*)(resid + (size_t)rg * 256 + c);
                        a0 += q.x; a1 += q.y;
                    }
                    vsum[tm * 2 + rh] += a0 + a1;
                    vsq[tm * 2 + rh] += a0 * a0 + a1 * a1;
                } else {
                    a0 = fmaxf(a0, 0.f); a1 = fmaxf(a1, 0.f);
                }
                acc[tm][tn][rh * 2 + 0] = a0;
                acc[tm][tn][rh * 2 + 1] = a1;
            }
        }
    }

    if (MODE == 0) {
#pragma unroll
        for (int k = 0; k < 4; ++k) {
            vsum[k] += __shfl_xor_sync(0xFFFFFFFFu, vsum[k], 1);
            vsum[k] += __shfl_xor_sync(0xFFFFFFFFu, vsum[k], 2);
            vsq[k]  += __shfl_xor_sync(0xFFFFFFFFu, vsq[k], 1);
            vsq[k]  += __shfl_xor_sync(0xFFFFFFFFu, vsq[k], 2);
        }
        if ((lane & 3) == 0) {
#pragma unroll
            for (int tm = 0; tm < 2; ++tm)
#pragma unroll
                for (int rh = 0; rh < 2; ++rh) {
                    int rloc = warpM * 32 + tm * 16 + rh * 8 + qrow;
                    atomicAdd(&rsum[rloc], vsum[tm * 2 + rh]);
                    atomicAdd(&rsq[rloc], vsq[tm * 2 + rh]);
                }
        }
        __syncthreads();
    }

#pragma unroll
    for (int tm = 0; tm < 2; ++tm) {
#pragma unroll
        for (int rh = 0; rh < 2; ++rh) {
            int rloc = warpM * 32 + tm * 16 + rh * 8 + qrow;
            int rg = row0 + rloc;
            if (rg >= M) continue;
            float mean = 0.f, inv = 1.f;
            if (MODE == 0) {
                mean = rsum[rloc] * (1.f / 256.f);
                inv = rsqrtf(rsq[rloc] * (1.f / 256.f) - mean * mean + 1e-5f);
            }
#pragma unroll
            for (int tn = 0; tn < 8; ++tn) {
                int c = warpN * 64 + tn * 8 + qc;
                float a0 = acc[tm][tn][rh * 2 + 0];
                float a1 = acc[tm][tn][rh * 2 + 1];
                if (MODE == 0) {
                    a0 = (a0 - mean) * inv * sgam[c] + sbet[c];
                    a1 = (a1 - mean) * inv * sgam[c + 1] + sbet[c + 1];
                    *(float2*)(outf + (size_t)rg * 256 + c) = make_float2(a0, a1);
                    if (outh != nullptr) {
                        uint32_t lw;
                        uint32_t hw = pack2bf(a0, a1, lw);
                        ((uint32_t*)outh)[((size_t)rg * 256 + c) >> 1] = hw;
                        ((uint32_t*)outl)[((size_t)rg * 256 + c) >> 1] = lw;
                    }
                } else {
                    uint32_t lw;
                    uint32_t hw = pack2bf(a0, a1, lw);
                    size_t off = ((size_t)rg * HF + col0 + c) >> 1;
                    ((uint32_t*)outh)[off] = hw;
                    ((uint32_t*)outl)[off] = lw;
                }
            }
        }
    }
}

// ------------------------------ launch --------------------------------------
extern "C" void kernel_launch(void* const* d_in, const int* in_sizes, int n_in,
                              void* d_out, int out_size) {
    const float* x      = (const float*)d_in[0];
    const int*   ei     = (const int*)d_in[1];
    const float* W_nbr  = (const float*)d_in[2];
    const float* W_root = (const float*)d_in[3];
    const float* b_gnn  = (const float*)d_in[4];
    const float* W1     = (const float*)d_in[5];
    const float* b1     = (const float*)d_in[6];
    const float* W2     = (const float*)d_in[7];
    const float* b2     = (const float*)d_in[8];
    const float* g1     = (const float*)d_in[9];
    const float* be1    = (const float*)d_in[10];
    const float* g2     = (const float*)d_in[11];
    const float* be2    = (const float*)d_in[12];
    float* out = (float*)d_out;

    const int M = in_sizes[0] / HD;
    const int E = in_sizes[1] / 2;

    float *agg, *h;
    __nv_bfloat16 *xh, *xl, *agh, *agl, *hh, *hl, *th, *tl;
    __nv_bfloat16 *wnh, *wnl, *wrh, *wrl, *w1h, *w1l, *w2h, *w2l;
    cudaGetSymbolAddress((void**)&agg, g_agg);
    cudaGetSymbolAddress((void**)&h, g_h);
    cudaGetSymbolAddress((void**)&xh, g_x_h);  cudaGetSymbolAddress((void**)&xl, g_x_l);
    cudaGetSymbolAddress((void**)&agh, g_ag_h); cudaGetSymbolAddress((void**)&agl, g_ag_l);
    cudaGetSymbolAddress((void**)&hh, g_h_h);  cudaGetSymbolAddress((void**)&hl, g_h_l);
    cudaGetSymbolAddress((void**)&th, g_t_h);  cudaGetSymbolAddress((void**)&tl, g_t_l);
    cudaGetSymbolAddress((void**)&wnh, g_wn_h); cudaGetSymbolAddress((void**)&wnl, g_wn_l);
    cudaGetSymbolAddress((void**)&wrh, g_wr_h); cudaGetSymbolAddress((void**)&wrl, g_wr_l);
    cudaGetSymbolAddress((void**)&w1h, g_w1_h); cudaGetSymbolAddress((void**)&w1l, g_w1_l);
    cudaGetSymbolAddress((void**)&w2h, g_w2_h); cudaGetSymbolAddress((void**)&w2l, g_w2_l);

    cudaFuncSetAttribute(gemm_mma<0>, cudaFuncAttributeMaxDynamicSharedMemorySize, SMEM_TOTAL);
    cudaFuncSetAttribute(gemm_mma<1>, cudaFuncAttributeMaxDynamicSharedMemorySize, SMEM_TOTAL);

    int n4 = M * HD / 4;
    zero_kernel<<<(n4 + 255) / 256, 256>>>(agg, n4);
    detect_kernel<<<1, 1>>>(ei, 2 * E);
    scatter_kernel<<<(E + 7) / 8, 256>>>(ei, E, x, agg);

    split_kernel<<<(n4 + 255) / 256, 256>>>(x, xh, xl, n4);
    split_kernel<<<(n4 + 255) / 256, 256>>>(agg, agh, agl, n4);
    tsplit_kernel<<<(HD * HD + 255) / 256, 256>>>(W_nbr, wnh, wnl, HD, HD);
    tsplit_kernel<<<(HD * HD + 255) / 256, 256>>>(W_root, wrh, wrl, HD, HD);
    tsplit_kernel<<<(HD * HF + 255) / 256, 256>>>(W1, w1h, w1l, HD, HF);
    tsplit_kernel<<<(HD * HF + 255) / 256, 256>>>(W2, w2h, w2l, HF, HD);

    int gx = (M + 63) / 64;

    // h = LN1(x + agg@Wnbr + x@Wroot + b_gnn), also emit hi/lo split of h
    gemm_mma<0><<<dim3(gx, 1), 256, SMEM_TOTAL>>>(
        agh, agl, wnh, wnl, HD, xh, xl, wrh, wrl, HD,
        b_gnn, x, g1, be1, h, hh, hl, M);

    // t = relu(h@W1 + b1)  (bf16 hi/lo only)
    gemm_mma<1><<<dim3(gx, 2), 256, SMEM_TOTAL>>>(
        hh, hl, w1h, w1l, HD, nullptr, nullptr, nullptr, nullptr, 0,
        b1, nullptr, nullptr, nullptr, nullptr, th, tl, M);

    // out = LN2(h + t@W2 + b2)
    gemm_mma<0><<<dim3(gx, 1), 256, SMEM_TOTAL>>>(
        th, tl, w2h, w2l, HF, nullptr, nullptr, nullptr, nullptr, 0,
        b2, h, g2, be2, out, nullptr, nullptr, M);
}

// round 4
// speedup vs baseline: 2.0174x; 1.2673x over previous
#include <cuda_runtime.h>
#include <cuda_fp16.h>
#include <cstdint>

#define HD 256
#define HF 512
#define NMAX 50000

// ------------------------- scratch (device globals) ------------------------
__device__ float g_agg[(size_t)NMAX * HD];
__device__ float g_h[(size_t)NMAX * HD];
__device__ __half g_x_h[(size_t)NMAX * HD];
__device__ __half g_x_l[(size_t)NMAX * HD];
__device__ __half g_ag_h[(size_t)NMAX * HD];
__device__ __half g_ag_l[(size_t)NMAX * HD];
__device__ __half g_h_h[(size_t)NMAX * HD];
__device__ __half g_h_l[(size_t)NMAX * HD];
__device__ __half g_t_h[(size_t)NMAX * HF];
__device__ __half g_t_l[(size_t)NMAX * HF];
__device__ __half g_wn_h[HD * HD];
__device__ __half g_wr_h[HD * HD];
__device__ __half g_w1_h[HD * HF];
__device__ __half g_w2_h[HD * HF];
__device__ int g_is64;

// ----------------------------- helpers -------------------------------------
__device__ __forceinline__ uint32_t smem_u32(const void* p) {
    uint32_t a;
    asm("{ .reg .u64 t; cvta.to.shared.u64 t, %1; cvt.u32.u64 %0, t; }" : "=r"(a) : "l"(p));
    return a;
}
__device__ __forceinline__ void ldsm_x4(uint32_t* r, uint32_t addr) {
    asm volatile("ldmatrix.sync.aligned.m8n8.x4.shared.b16 {%0,%1,%2,%3}, [%4];"
                 : "=r"(r[0]), "=r"(r[1]), "=r"(r[2]), "=r"(r[3]) : "r"(addr));
}
__device__ __forceinline__ void ldsm_x2(uint32_t* r, uint32_t addr) {
    asm volatile("ldmatrix.sync.aligned.m8n8.x2.shared.b16 {%0,%1}, [%2];"
                 : "=r"(r[0]), "=r"(r[1]) : "r"(addr));
}
__device__ __forceinline__ void mma_f16(float* d, const uint32_t* a, const uint32_t* b) {
    asm volatile(
        "mma.sync.aligned.m16n8k16.row.col.f32.f16.f16.f32 "
        "{%0,%1,%2,%3}, {%4,%5,%6,%7}, {%8,%9}, {%0,%1,%2,%3};"
        : "+f"(d[0]), "+f"(d[1]), "+f"(d[2]), "+f"(d[3])
        : "r"(a[0]), "r"(a[1]), "r"(a[2]), "r"(a[3]), "r"(b[0]), "r"(b[1]));
}
__device__ __forceinline__ void cp_async16(uint32_t dst, const void* src, int szr) {
    asm volatile("cp.async.cg.shared.global [%0], [%1], 16, %2;"
                 :: "r"(dst), "l"(src), "r"(szr) : "memory");
}
#define CP_COMMIT() asm volatile("cp.async.commit_group;" ::: "memory")
#define CP_WAIT1()  asm volatile("cp.async.wait_group 1;" ::: "memory")
#define CP_WAIT0()  asm volatile("cp.async.wait_group 0;" ::: "memory")

__device__ __forceinline__ uint32_t pack2hf(float a, float b, uint32_t& lopack) {
    __half ha = __float2half_rn(a), hb = __float2half_rn(b);
    float la = a - __half2float(ha), lb = b - __half2float(hb);
    __half lA = __float2half_rn(la), lB = __float2half_rn(lb);
    lopack = (uint32_t)__half_as_ushort(lA) | ((uint32_t)__half_as_ushort(lB) << 16);
    return (uint32_t)__half_as_ushort(ha) | ((uint32_t)__half_as_ushort(hb) << 16);
}

// --------------------------- small kernels ---------------------------------
__global__ void zero_kernel(float* __restrict__ p, int n4) {
    int i = blockIdx.x * blockDim.x + threadIdx.x;
    if (i < n4) ((float4*)p)[i] = make_float4(0.f, 0.f, 0.f, 0.f);
}

__global__ void detect_kernel(const int* __restrict__ ei, int twoE) {
    int nz = 0;
    int lim = twoE * 2;
    if (lim > 256) lim = 256;
    for (int i = 1; i < lim; i += 2) nz |= ei[i];
    g_is64 = (nz == 0) ? 1 : 0;
}

// read fp16 hi part of x (half the read traffic), fp32 vector-RED into agg
__global__ void scatter_kernel(const int* __restrict__ ei, int E,
                               const __half* __restrict__ xh,
                               float* __restrict__ agg) {
    int warp = (blockIdx.x * blockDim.x + threadIdx.x) >> 5;
    int lane = threadIdx.x & 31;
    if (warp >= E) return;
    int s, d;
    if (g_is64) { s = ei[2 * warp]; d = ei[2 * (E + warp)]; }
    else        { s = ei[warp];     d = ei[E + warp]; }
    const uint4* xs = (const uint4*)(xh + (size_t)s * HD);
    float* ad = agg + (size_t)d * HD + lane * 8;
    uint4 v = xs[lane];
    float2 f0 = __half22float2(*(const __half2*)&v.x);
    float2 f1 = __half22float2(*(const __half2*)&v.y);
    float2 f2 = __half22float2(*(const __half2*)&v.z);
    float2 f3 = __half22float2(*(const __half2*)&v.w);
    asm volatile("red.global.add.v4.f32 [%0], {%1,%2,%3,%4};"
                 :: "l"(ad), "f"(f0.x), "f"(f0.y), "f"(f1.x), "f"(f1.y) : "memory");
    asm volatile("red.global.add.v4.f32 [%0], {%1,%2,%3,%4};"
                 :: "l"(ad + 4), "f"(f2.x), "f"(f2.y), "f"(f3.x), "f"(f3.y) : "memory");
}

__global__ void split_kernel(const float* __restrict__ in,
                             __half* __restrict__ oh,
                             __half* __restrict__ ol, int n4) {
    int i = blockIdx.x * blockDim.x + threadIdx.x;
    if (i >= n4) return;
    float4 v = ((const float4*)in)[i];
    uint32_t l0, l1;
    uint32_t h0 = pack2hf(v.x, v.y, l0);
    uint32_t h1 = pack2hf(v.z, v.w, l1);
    ((uint2*)oh)[i] = make_uint2(h0, h1);
    ((uint2*)ol)[i] = make_uint2(l0, l1);
}

// W [K,N] -> out [N,K] fp16 (single, rounded)
__global__ void tsplit_kernel(const float* __restrict__ W,
                              __half* __restrict__ oh, int K, int N) {
    int idx = blockIdx.x * blockDim.x + threadIdx.x;
    if (idx >= K * N) return;
    int n = idx / K, k = idx - n * K;
    oh[idx] = __float2half_rn(W[(size_t)k * N + n]);
}

// ----------------------- fp16 2-term mma.sync GEMM -------------------------
// BM=64, BN=256, BK=32, 256 threads, 3-stage cp.async pipeline, 2 CTAs/SM.
// stage: A (64 rows hi + 64 rows lo) x 80B = 10240B, B (256 rows) x 80B = 20480B
#define STAGE_BYTES 30720
#define SMEM_TOTAL  (3 * STAGE_BYTES)

__device__ __forceinline__ void load_stage(
    uint32_t sa, int tid, int row0, int col0,
    const __half* Ah, const __half* Al, const __half* Bh,
    int K, int kc, int M) {
#pragma unroll
    for (int j = 0; j < 2; ++j) {   // A: 512 chunks of 16B (hi 64 rows, lo 64 rows)
        int id = tid + j * 256;
        int r = id >> 2, c = id & 3;
        int row = row0 + (r & 63);
        int szr = (row < M) ? 16 : 0;
        size_t roff = (row < M) ? (size_t)row : 0;
        const __half* src = (r < 64 ? Ah : Al) + roff * K + kc + c * 8;
        cp_async16(sa + r * 80 + c * 16, src, szr);
    }
    uint32_t sb = sa + 10240;
#pragma unroll
    for (int j = 0; j < 4; ++j) {   // B: 1024 chunks
        int id = tid + j * 256;
        int r = id >> 2, c = id & 3;
        int n = col0 + r;
        const __half* src = Bh + (size_t)n * K + kc + c * 8;
        cp_async16(sb + r * 80 + c * 16, src, 16);
    }
}

// MODE 0: C = A@B(+A1@B1) + bias + resid -> LN(gamma,beta) -> outf (+opt hi/lo)
// MODE 1: C = relu(A@B + bias) -> hi/lo split only (stride HF)
template <int MODE>
__global__ void __launch_bounds__(256, 2)
gemm_mma(const __half* __restrict__ A0h, const __half* __restrict__ A0l,
         const __half* __restrict__ B0h, int K0,
         const __half* __restrict__ A1h, const __half* __restrict__ A1l,
         const __half* __restrict__ B1h, int K1,
         const float* __restrict__ bias, const float* __restrict__ resid,
         const float* __restrict__ gamma, const float* __restrict__ beta,
         float* __restrict__ outf, __half* __restrict__ outh,
         __half* __restrict__ outl, int M) {
    extern __shared__ char smem[];
    const uint32_t sb0 = smem_u32(smem);
    const int tid = threadIdx.x;
    const int lane = tid & 31;
    const int warp = tid >> 5;
    const int warpM = warp >> 2;     // 0..1
    const int warpN = warp & 3;      // 0..3
    const int row0 = blockIdx.x * 64;
    const int col0 = blockIdx.y * 256;

    float acc[2][8][4];
#pragma unroll
    for (int i = 0; i < 2; ++i)
#pragma unroll
        for (int j = 0; j < 8; ++j)
#pragma unroll
            for (int k = 0; k < 4; ++k) acc[i][j][k] = 0.f;

    const int S = (K0 + K1) >> 5;

    const uint32_t aoff = (uint32_t)((warpM * 32 + (lane & 7) + ((lane >> 3) & 1) * 8) * 80
                                     + (lane >> 4) * 16);
    const uint32_t boff = (uint32_t)((warpN * 64 + (lane & 7)) * 80 + ((lane >> 3) & 1) * 16);

#define RESOLVE(IT, AH, AL, BH, KK, KC)                                  \
    { int kt = (IT) * 32;                                                \
      if (kt < K0) { AH = A0h; AL = A0l; BH = B0h; KK = K0; KC = kt; }   \
      else         { AH = A1h; AL = A1l; BH = B1h; KK = K1; KC = kt - K0; } }

    {
        const __half *Ah, *Al, *Bh; int KK, KC;
        RESOLVE(0, Ah, Al, Bh, KK, KC);
        load_stage(sb0, tid, row0, col0, Ah, Al, Bh, KK, KC, M);
        CP_COMMIT();
        if (S > 1) {
            RESOLVE(1, Ah, Al, Bh, KK, KC);
            load_stage(sb0 + STAGE_BYTES, tid, row0, col0, Ah, Al, Bh, KK, KC, M);
        }
        CP_COMMIT();
    }

    int stage = 0;
    for (int it = 0; it < S; ++it) {
        CP_WAIT1();
        __syncthreads();
        if (it + 2 < S) {
            int s2 = stage + 2; if (s2 >= 3) s2 -= 3;
            const __half *Ah, *Al, *Bh; int KK, KC;
            RESOLVE(it + 2, Ah, Al, Bh, KK, KC);
            load_stage(sb0 + s2 * STAGE_BYTES, tid, row0, col0, Ah, Al, Bh, KK, KC, M);
        }
        CP_COMMIT();

        const uint32_t sa = sb0 + stage * STAGE_BYTES;
        const uint32_t sbB = sa + 10240;
#pragma unroll
        for (int ks = 0; ks < 2; ++ks) {
            uint32_t ah[2][4], al[2][4];
#pragma unroll
            for (int tm = 0; tm < 2; ++tm) {
                uint32_t base = sa + aoff + tm * 1280 + ks * 32;
                ldsm_x4(ah[tm], base);
                ldsm_x4(al[tm], base + 5120);
            }
#pragma unroll
            for (int tn = 0; tn < 8; ++tn) {
                uint32_t bh[2];
                ldsm_x2(bh, sbB + boff + tn * 640 + ks * 32);
#pragma unroll
                for (int tm = 0; tm < 2; ++tm) {
                    mma_f16(acc[tm][tn], ah[tm], bh);
                    mma_f16(acc[tm][tn], al[tm], bh);
                }
            }
        }
        ++stage; if (stage == 3) stage = 0;
    }

    CP_WAIT0();
    __syncthreads();

    // ---------------------------- epilogue ---------------------------------
    float* rsum  = (float*)smem;        // 64
    float* rsq   = rsum + 64;           // 64
    float* sbias = rsq + 64;            // 256
    float* sgam  = sbias + 256;
    float* sbet  = sgam + 256;
    if (MODE == 0 && tid < 64) { rsum[tid] = 0.f; rsq[tid] = 0.f; }
    sbias[tid] = bias[col0 + tid];
    if (MODE == 0) { sgam[tid] = gamma[tid]; sbet[tid] = beta[tid]; }
    __syncthreads();

    const int qrow = lane >> 2;
    const int qc = (lane & 3) * 2;

    float vsum[4], vsq[4];
#pragma unroll
    for (int k = 0; k < 4; ++k) { vsum[k] = 0.f; vsq[k] = 0.f; }

#pragma unroll
    for (int tm = 0; tm < 2; ++tm) {
#pragma unroll
        for (int rh = 0; rh < 2; ++rh) {
            int rloc = warpM * 32 + tm * 16 + rh * 8 + qrow;
            int rg = row0 + rloc;
            bool v = rg < M;
#pragma unroll
            for (int tn = 0; tn < 8; ++tn) {
                int c = warpN * 64 + tn * 8 + qc;
                float a0 = acc[tm][tn][rh * 2 + 0] + sbias[c];
                float a1 = acc[tm][tn][rh * 2 + 1] + sbias[c + 1];
                if (MODE == 0) {
                    if (v) {
                        float2 q = *(const float2*)(resid + (size_t)rg * 256 + c);
                        a0 += q.x; a1 += q.y;
                    }
                    vsum[tm * 2 + rh] += a0 + a1;
                    vsq[tm * 2 + rh] += a0 * a0 + a1 * a1;
                } else {
                    a0 = fmaxf(a0, 0.f); a1 = fmaxf(a1, 0.f);
                }
                acc[tm][tn][rh * 2 + 0] = a0;
                acc[tm][tn][rh * 2 + 1] = a1;
            }
        }
    }

    if (MODE == 0) {
#pragma unroll
        for (int k = 0; k < 4; ++k) {
            vsum[k] += __shfl_xor_sync(0xFFFFFFFFu, vsum[k], 1);
            vsum[k] += __shfl_xor_sync(0xFFFFFFFFu, vsum[k], 2);
            vsq[k]  += __shfl_xor_sync(0xFFFFFFFFu, vsq[k], 1);
            vsq[k]  += __shfl_xor_sync(0xFFFFFFFFu, vsq[k], 2);
        }
        if ((lane & 3) == 0) {
#pragma unroll
            for (int tm = 0; tm < 2; ++tm)
#pragma unroll
                for (int rh = 0; rh < 2; ++rh) {
                    int rloc = warpM * 32 + tm * 16 + rh * 8 + qrow;
                    atomicAdd(&rsum[rloc], vsum[tm * 2 + rh]);
                    atomicAdd(&rsq[rloc], vsq[tm * 2 + rh]);
                }
        }
        __syncthreads();
    }

#pragma unroll
    for (int tm = 0; tm < 2; ++tm) {
#pragma unroll
        for (int rh = 0; rh < 2; ++rh) {
            int rloc = warpM * 32 + tm * 16 + rh * 8 + qrow;
            int rg = row0 + rloc;
            if (rg >= M) continue;
            float mean = 0.f, inv = 1.f;
            if (MODE == 0) {
                mean = rsum[rloc] * (1.f / 256.f);
                inv = rsqrtf(rsq[rloc] * (1.f / 256.f) - mean * mean + 1e-5f);
            }
#pragma unroll
            for (int tn = 0; tn < 8; ++tn) {
                int c = warpN * 64 + tn * 8 + qc;
                float a0 = acc[tm][tn][rh * 2 + 0];
                float a1 = acc[tm][tn][rh * 2 + 1];
                if (MODE == 0) {
                    a0 = (a0 - mean) * inv * sgam[c] + sbet[c];
                    a1 = (a1 - mean) * inv * sgam[c + 1] + sbet[c + 1];
                    *(float2*)(outf + (size_t)rg * 256 + c) = make_float2(a0, a1);
                    if (outh != nullptr) {
                        uint32_t lw;
                        uint32_t hw = pack2hf(a0, a1, lw);
                        ((uint32_t*)outh)[((size_t)rg * 256 + c) >> 1] = hw;
                        ((uint32_t*)outl)[((size_t)rg * 256 + c) >> 1] = lw;
                    }
                } else {
                    uint32_t lw;
                    uint32_t hw = pack2hf(a0, a1, lw);
                    size_t off = ((size_t)rg * HF + col0 + c) >> 1;
                    ((uint32_t*)outh)[off] = hw;
                    ((uint32_t*)outl)[off] = lw;
                }
            }
        }
    }
}

// ------------------------------ launch --------------------------------------
extern "C" void kernel_launch(void* const* d_in, const int* in_sizes, int n_in,
                              void* d_out, int out_size) {
    const float* x      = (const float*)d_in[0];
    const int*   ei     = (const int*)d_in[1];
    const float* W_nbr  = (const float*)d_in[2];
    const float* W_root = (const float*)d_in[3];
    const float* b_gnn  = (const float*)d_in[4];
    const float* W1     = (const float*)d_in[5];
    const float* b1     = (const float*)d_in[6];
    const float* W2     = (const float*)d_in[7];
    const float* b2     = (const float*)d_in[8];
    const float* g1     = (const float*)d_in[9];
    const float* be1    = (const float*)d_in[10];
    const float* g2     = (const float*)d_in[11];
    const float* be2    = (const float*)d_in[12];
    float* out = (float*)d_out;

    const int M = in_sizes[0] / HD;
    const int E = in_sizes[1] / 2;

    float *agg, *h;
    __half *xh, *xl, *agh, *agl, *hh, *hl, *th, *tl;
    __half *wnh, *wrh, *w1h, *w2h;
    cudaGetSymbolAddress((void**)&agg, g_agg);
    cudaGetSymbolAddress((void**)&h, g_h);
    cudaGetSymbolAddress((void**)&xh, g_x_h);  cudaGetSymbolAddress((void**)&xl, g_x_l);
    cudaGetSymbolAddress((void**)&agh, g_ag_h); cudaGetSymbolAddress((void**)&agl, g_ag_l);
    cudaGetSymbolAddress((void**)&hh, g_h_h);  cudaGetSymbolAddress((void**)&hl, g_h_l);
    cudaGetSymbolAddress((void**)&th, g_t_h);  cudaGetSymbolAddress((void**)&tl, g_t_l);
    cudaGetSymbolAddress((void**)&wnh, g_wn_h);
    cudaGetSymbolAddress((void**)&wrh, g_wr_h);
    cudaGetSymbolAddress((void**)&w1h, g_w1_h);
    cudaGetSymbolAddress((void**)&w2h, g_w2_h);

    cudaFuncSetAttribute(gemm_mma<0>, cudaFuncAttributeMaxDynamicSharedMemorySize, SMEM_TOTAL);
    cudaFuncSetAttribute(gemm_mma<1>, cudaFuncAttributeMaxDynamicSharedMemorySize, SMEM_TOTAL);

    int n4 = M * HD / 4;
    // split x first: scatter reads fp16 xh
    split_kernel<<<(n4 + 255) / 256, 256>>>(x, xh, xl, n4);
    zero_kernel<<<(n4 + 255) / 256, 256>>>(agg, n4);
    detect_kernel<<<1, 1>>>(ei, 2 * E);
    scatter_kernel<<<(E + 7) / 8, 256>>>(ei, E, xh, agg);
    split_kernel<<<(n4 + 255) / 256, 256>>>(agg, agh, agl, n4);

    tsplit_kernel<<<(HD * HD + 255) / 256, 256>>>(W_nbr, wnh, HD, HD);
    tsplit_kernel<<<(HD * HD + 255) / 256, 256>>>(W_root, wrh, HD, HD);
    tsplit_kernel<<<(HD * HF + 255) / 256, 256>>>(W1, w1h, HD, HF);
    tsplit_kernel<<<(HD * HF + 255) / 256, 256>>>(W2, w2h, HF, HD);

    int gx = (M + 63) / 64;

    // h = LN1(x + agg@Wnbr + x@Wroot + b_gnn), emit fp16 hi/lo of h
    gemm_mma<0><<<dim3(gx, 1), 256, SMEM_TOTAL>>>(
        agh, agl, wnh, HD, xh, xl, wrh, HD,
        b_gnn, x, g1, be1, h, hh, hl, M);

    // t = relu(h@W1 + b1) (fp16 hi/lo only)
    gemm_mma<1><<<dim3(gx, 2), 256, SMEM_TOTAL>>>(
        hh, hl, w1h, HD, nullptr, nullptr, nullptr, 0,
        b1, nullptr, nullptr, nullptr, nullptr, th, tl, M);

    // out = LN2(h + t@W2 + b2)
    gemm_mma<0><<<dim3(gx, 1), 256, SMEM_TOTAL>>>(
        th, tl, w2h, HF, nullptr, nullptr, nullptr, 0,
        b2, h, g2, be2, out, nullptr, nullptr, M);
}

// round 5
// speedup vs baseline: 2.4612x; 1.2200x over previous
#include <cuda_runtime.h>
#include <cuda_fp16.h>
#include <cstdint>

#define HD 256
#define HF 512
#define NMAX 50000
#define EMAX 800000

// ------------------------- scratch (device globals) ------------------------
__device__ float g_h[(size_t)NMAX * HD];
__device__ __half g_x_h[(size_t)NMAX * HD];
__device__ __half g_x_l[(size_t)NMAX * HD];
__device__ __half g_ag_h[(size_t)NMAX * HD];
__device__ __half g_ag_l[(size_t)NMAX * HD];
__device__ __half g_h_h[(size_t)NMAX * HD];
__device__ __half g_h_l[(size_t)NMAX * HD];
__device__ __half g_t_h[(size_t)NMAX * HF];
__device__ __half g_t_l[(size_t)NMAX * HF];
__device__ __half g_wn_h[HD * HD];
__device__ __half g_wr_h[HD * HD];
__device__ __half g_w1_h[HD * HF];
__device__ __half g_w2_h[HD * HF];
__device__ int g_deg[NMAX];
__device__ int g_off[NMAX + 1];
__device__ int g_cur[NMAX];
__device__ int g_srcl[EMAX];
__device__ int g_is64;

// ----------------------------- helpers -------------------------------------
__device__ __forceinline__ uint32_t smem_u32(const void* p) {
    uint32_t a;
    asm("{ .reg .u64 t; cvta.to.shared.u64 t, %1; cvt.u32.u64 %0, t; }" : "=r"(a) : "l"(p));
    return a;
}
__device__ __forceinline__ void ldsm_x4(uint32_t* r, uint32_t addr) {
    asm volatile("ldmatrix.sync.aligned.m8n8.x4.shared.b16 {%0,%1,%2,%3}, [%4];"
                 : "=r"(r[0]), "=r"(r[1]), "=r"(r[2]), "=r"(r[3]) : "r"(addr));
}
__device__ __forceinline__ void ldsm_x2(uint32_t* r, uint32_t addr) {
    asm volatile("ldmatrix.sync.aligned.m8n8.x2.shared.b16 {%0,%1}, [%2];"
                 : "=r"(r[0]), "=r"(r[1]) : "r"(addr));
}
__device__ __forceinline__ void mma_f16(float* d, const uint32_t* a, const uint32_t* b) {
    asm volatile(
        "mma.sync.aligned.m16n8k16.row.col.f32.f16.f16.f32 "
        "{%0,%1,%2,%3}, {%4,%5,%6,%7}, {%8,%9}, {%0,%1,%2,%3};"
        : "+f"(d[0]), "+f"(d[1]), "+f"(d[2]), "+f"(d[3])
        : "r"(a[0]), "r"(a[1]), "r"(a[2]), "r"(a[3]), "r"(b[0]), "r"(b[1]));
}
__device__ __forceinline__ void cp_async16(uint32_t dst, const void* src, int szr) {
    asm volatile("cp.async.cg.shared.global [%0], [%1], 16, %2;"
                 :: "r"(dst), "l"(src), "r"(szr) : "memory");
}
#define CP_COMMIT() asm volatile("cp.async.commit_group;" ::: "memory")
#define CP_WAIT1()  asm volatile("cp.async.wait_group 1;" ::: "memory")
#define CP_WAIT0()  asm volatile("cp.async.wait_group 0;" ::: "memory")

__device__ __forceinline__ uint32_t pack2hf(float a, float b, uint32_t& lopack) {
    __half ha = __float2half_rn(a), hb = __float2half_rn(b);
    float la = a - __half2float(ha), lb = b - __half2float(hb);
    __half lA = __float2half_rn(la), lB = __float2half_rn(lb);
    lopack = (uint32_t)__half_as_ushort(lA) | ((uint32_t)__half_as_ushort(lB) << 16);
    return (uint32_t)__half_as_ushort(ha) | ((uint32_t)__half_as_ushort(hb) << 16);
}

// --------------------------- small kernels ---------------------------------
__global__ void detect_kernel(const int* __restrict__ ei, int twoE) {
    int nz = 0;
    int lim = twoE * 2;
    if (lim > 256) lim = 256;
    for (int i = 1; i < lim; i += 2) nz |= ei[i];
    g_is64 = (nz == 0) ? 1 : 0;
}

__global__ void zero_deg_kernel(int* __restrict__ deg, int M) {
    int i = blockIdx.x * blockDim.x + threadIdx.x;
    if (i < M) deg[i] = 0;
}

__global__ void hist_kernel(const int* __restrict__ ei, int E, int* __restrict__ deg) {
    int e = blockIdx.x * blockDim.x + threadIdx.x;
    if (e >= E) return;
    int d = g_is64 ? ei[2 * (E + e)] : ei[E + e];
    atomicAdd(&deg[d], 1);
}

// one-block exclusive scan over degrees
__global__ void scan_kernel(const int* __restrict__ deg, int* __restrict__ off,
                            int* __restrict__ cur, int M) {
    __shared__ int part[1024];
    const int t = threadIdx.x;
    const int chunk = (M + 1023) / 1024;
    int c0 = t * chunk, c1 = min(c0 + chunk, M);
    int s = 0;
    for (int i = c0; i < c1; ++i) s += deg[i];
    part[t] = s;
    __syncthreads();
    if (t == 0) {
        int r = 0;
        for (int i = 0; i < 1024; ++i) { int v = part[i]; part[i] = r; r += v; }
    }
    __syncthreads();
    int run = part[t];
    for (int i = c0; i < c1; ++i) {
        off[i] = run; cur[i] = run; run += deg[i];
    }
    if (c1 == M && c0 < M) off[M] = run;
    if (M <= c0 && t == 0) off[M] = 0;   // degenerate
}

__global__ void fill_kernel(const int* __restrict__ ei, int E,
                            int* __restrict__ cur, int* __restrict__ srcl) {
    int e = blockIdx.x * blockDim.x + threadIdx.x;
    if (e >= E) return;
    int s, d;
    if (g_is64) { s = ei[2 * e]; d = ei[2 * (E + e)]; }
    else        { s = ei[e];     d = ei[E + e]; }
    int pos = atomicAdd(&cur[d], 1);
    srcl[pos] = s;
}

// gather: one warp per node; unroll-8 neighbor batches for MLP;
// emit fp16 hi/lo split of agg directly.
__global__ void __launch_bounds__(256)
gather_kernel(const int* __restrict__ off, const int* __restrict__ srcl,
              const __half* __restrict__ xh,
              __half* __restrict__ agh, __half* __restrict__ agl, int M) {
    int node = blockIdx.x * 8 + (threadIdx.x >> 5);
    int lane = threadIdx.x & 31;
    if (node >= M) return;
    int j0 = off[node], j1 = off[node + 1];

    float acc[8];
#pragma unroll
    for (int k = 0; k < 8; ++k) acc[k] = 0.f;

    const uint4* xb = (const uint4*)xh;
    int j = j0;
    for (; j + 8 <= j1; j += 8) {
        int srcs[8];
#pragma unroll
        for (int u = 0; u < 8; ++u) srcs[u] = srcl[j + u];
        uint4 v[8];
#pragma unroll
        for (int u = 0; u < 8; ++u) v[u] = xb[(size_t)srcs[u] * 32 + lane];
#pragma unroll
        for (int u = 0; u < 8; ++u) {
            float2 f0 = __half22float2(*(const __half2*)&v[u].x);
            float2 f1 = __half22float2(*(const __half2*)&v[u].y);
            float2 f2 = __half22float2(*(const __half2*)&v[u].z);
            float2 f3 = __half22float2(*(const __half2*)&v[u].w);
            acc[0] += f0.x; acc[1] += f0.y; acc[2] += f1.x; acc[3] += f1.y;
            acc[4] += f2.x; acc[5] += f2.y; acc[6] += f3.x; acc[7] += f3.y;
        }
    }
    for (; j < j1; ++j) {
        uint4 v = xb[(size_t)srcl[j] * 32 + lane];
        float2 f0 = __half22float2(*(const __half2*)&v.x);
        float2 f1 = __half22float2(*(const __half2*)&v.y);
        float2 f2 = __half22float2(*(const __half2*)&v.z);
        float2 f3 = __half22float2(*(const __half2*)&v.w);
        acc[0] += f0.x; acc[1] += f0.y; acc[2] += f1.x; acc[3] += f1.y;
        acc[4] += f2.x; acc[5] += f2.y; acc[6] += f3.x; acc[7] += f3.y;
    }

    uint32_t hi[4], lo[4];
#pragma unroll
    for (int k = 0; k < 4; ++k) hi[k] = pack2hf(acc[2 * k], acc[2 * k + 1], lo[k]);
    size_t o = (size_t)node * 32 + lane;
    ((uint4*)agh)[o] = make_uint4(hi[0], hi[1], hi[2], hi[3]);
    ((uint4*)agl)[o] = make_uint4(lo[0], lo[1], lo[2], lo[3]);
}

__global__ void split_kernel(const float* __restrict__ in,
                             __half* __restrict__ oh,
                             __half* __restrict__ ol, int n4) {
    int i = blockIdx.x * blockDim.x + threadIdx.x;
    if (i >= n4) return;
    float4 v = ((const float4*)in)[i];
    uint32_t l0, l1;
    uint32_t h0 = pack2hf(v.x, v.y, l0);
    uint32_t h1 = pack2hf(v.z, v.w, l1);
    ((uint2*)oh)[i] = make_uint2(h0, h1);
    ((uint2*)ol)[i] = make_uint2(l0, l1);
}

// W [K,N] -> out [N,K] fp16 (single, rounded)
__global__ void tsplit_kernel(const float* __restrict__ W,
                              __half* __restrict__ oh, int K, int N) {
    int idx = blockIdx.x * blockDim.x + threadIdx.x;
    if (idx >= K * N) return;
    int n = idx / K, k = idx - n * K;
    oh[idx] = __float2half_rn(W[(size_t)k * N + n]);
}

// ----------------------- fp16 2-term mma.sync GEMM -------------------------
// BM=64, BN=256, BK=32, 256 threads, 3-stage cp.async pipeline, 2 CTAs/SM.
#define STAGE_BYTES 30720
#define SMEM_TOTAL  (3 * STAGE_BYTES)

__device__ __forceinline__ void load_stage(
    uint32_t sa, int tid, int row0, int col0,
    const __half* Ah, const __half* Al, const __half* Bh,
    int K, int kc, int M) {
#pragma unroll
    for (int j = 0; j < 2; ++j) {
        int id = tid + j * 256;
        int r = id >> 2, c = id & 3;
        int row = row0 + (r & 63);
        int szr = (row < M) ? 16 : 0;
        size_t roff = (row < M) ? (size_t)row : 0;
        const __half* src = (r < 64 ? Ah : Al) + roff * K + kc + c * 8;
        cp_async16(sa + r * 80 + c * 16, src, szr);
    }
    uint32_t sb = sa + 10240;
#pragma unroll
    for (int j = 0; j < 4; ++j) {
        int id = tid + j * 256;
        int r = id >> 2, c = id & 3;
        int n = col0 + r;
        const __half* src = Bh + (size_t)n * K + kc + c * 8;
        cp_async16(sb + r * 80 + c * 16, src, 16);
    }
}

template <int MODE>
__global__ void __launch_bounds__(256, 2)
gemm_mma(const __half* __restrict__ A0h, const __half* __restrict__ A0l,
         const __half* __restrict__ B0h, int K0,
         const __half* __restrict__ A1h, const __half* __restrict__ A1l,
         const __half* __restrict__ B1h, int K1,
         const float* __restrict__ bias, const float* __restrict__ resid,
         const float* __restrict__ gamma, const float* __restrict__ beta,
         float* __restrict__ outf, __half* __restrict__ outh,
         __half* __restrict__ outl, int M) {
    extern __shared__ char smem[];
    const uint32_t sb0 = smem_u32(smem);
    const int tid = threadIdx.x;
    const int lane = tid & 31;
    const int warp = tid >> 5;
    const int warpM = warp >> 2;
    const int warpN = warp & 3;
    const int row0 = blockIdx.x * 64;
    const int col0 = blockIdx.y * 256;

    float acc[2][8][4];
#pragma unroll
    for (int i = 0; i < 2; ++i)
#pragma unroll
        for (int j = 0; j < 8; ++j)
#pragma unroll
            for (int k = 0; k < 4; ++k) acc[i][j][k] = 0.f;

    const int S = (K0 + K1) >> 5;

    const uint32_t aoff = (uint32_t)((warpM * 32 + (lane & 7) + ((lane >> 3) & 1) * 8) * 80
                                     + (lane >> 4) * 16);
    const uint32_t boff = (uint32_t)((warpN * 64 + (lane & 7)) * 80 + ((lane >> 3) & 1) * 16);

#define RESOLVE(IT, AH, AL, BH, KK, KC)                                  \
    { int kt = (IT) * 32;                                                \
      if (kt < K0) { AH = A0h; AL = A0l; BH = B0h; KK = K0; KC = kt; }   \
      else         { AH = A1h; AL = A1l; BH = B1h; KK = K1; KC = kt - K0; } }

    {
        const __half *Ah, *Al, *Bh; int KK, KC;
        RESOLVE(0, Ah, Al, Bh, KK, KC);
        load_stage(sb0, tid, row0, col0, Ah, Al, Bh, KK, KC, M);
        CP_COMMIT();
        if (S > 1) {
            RESOLVE(1, Ah, Al, Bh, KK, KC);
            load_stage(sb0 + STAGE_BYTES, tid, row0, col0, Ah, Al, Bh, KK, KC, M);
        }
        CP_COMMIT();
    }

    int stage = 0;
    for (int it = 0; it < S; ++it) {
        CP_WAIT1();
        __syncthreads();
        if (it + 2 < S) {
            int s2 = stage + 2; if (s2 >= 3) s2 -= 3;
            const __half *Ah, *Al, *Bh; int KK, KC;
            RESOLVE(it + 2, Ah, Al, Bh, KK, KC);
            load_stage(sb0 + s2 * STAGE_BYTES, tid, row0, col0, Ah, Al, Bh, KK, KC, M);
        }
        CP_COMMIT();

        const uint32_t sa = sb0 + stage * STAGE_BYTES;
        const uint32_t sbB = sa + 10240;
#pragma unroll
        for (int ks = 0; ks < 2; ++ks) {
            uint32_t ah[2][4], al[2][4];
#pragma unroll
            for (int tm = 0; tm < 2; ++tm) {
                uint32_t base = sa + aoff + tm * 1280 + ks * 32;
                ldsm_x4(ah[tm], base);
                ldsm_x4(al[tm], base + 5120);
            }
#pragma unroll
            for (int tn = 0; tn < 8; ++tn) {
                uint32_t bh[2];
                ldsm_x2(bh, sbB + boff + tn * 640 + ks * 32);
#pragma unroll
                for (int tm = 0; tm < 2; ++tm) {
                    mma_f16(acc[tm][tn], ah[tm], bh);
                    mma_f16(acc[tm][tn], al[tm], bh);
                }
            }
        }
        ++stage; if (stage == 3) stage = 0;
    }

    CP_WAIT0();
    __syncthreads();

    // ---------------------------- epilogue ---------------------------------
    float* rsum  = (float*)smem;
    float* rsq   = rsum + 64;
    float* sbias = rsq + 64;
    float* sgam  = sbias + 256;
    float* sbet  = sgam + 256;
    if (MODE == 0 && tid < 64) { rsum[tid] = 0.f; rsq[tid] = 0.f; }
    sbias[tid] = bias[col0 + tid];
    if (MODE == 0) { sgam[tid] = gamma[tid]; sbet[tid] = beta[tid]; }
    __syncthreads();

    const int qrow = lane >> 2;
    const int qc = (lane & 3) * 2;

    float vsum[4], vsq[4];
#pragma unroll
    for (int k = 0; k < 4; ++k) { vsum[k] = 0.f; vsq[k] = 0.f; }

#pragma unroll
    for (int tm = 0; tm < 2; ++tm) {
#pragma unroll
        for (int rh = 0; rh < 2; ++rh) {
            int rloc = warpM * 32 + tm * 16 + rh * 8 + qrow;
            int rg = row0 + rloc;
            bool v = rg < M;
#pragma unroll
            for (int tn = 0; tn < 8; ++tn) {
                int c = warpN * 64 + tn * 8 + qc;
                float a0 = acc[tm][tn][rh * 2 + 0] + sbias[c];
                float a1 = acc[tm][tn][rh * 2 + 1] + sbias[c + 1];
                if (MODE == 0) {
                    if (v) {
                        float2 q = *(const float2*)(resid + (size_t)rg * 256 + c);
                        a0 += q.x; a1 += q.y;
                    }
                    vsum[tm * 2 + rh] += a0 + a1;
                    vsq[tm * 2 + rh] += a0 * a0 + a1 * a1;
                } else {
                    a0 = fmaxf(a0, 0.f); a1 = fmaxf(a1, 0.f);
                }
                acc[tm][tn][rh * 2 + 0] = a0;
                acc[tm][tn][rh * 2 + 1] = a1;
            }
        }
    }

    if (MODE == 0) {
#pragma unroll
        for (int k = 0; k < 4; ++k) {
            vsum[k] += __shfl_xor_sync(0xFFFFFFFFu, vsum[k], 1);
            vsum[k] += __shfl_xor_sync(0xFFFFFFFFu, vsum[k], 2);
            vsq[k]  += __shfl_xor_sync(0xFFFFFFFFu, vsq[k], 1);
            vsq[k]  += __shfl_xor_sync(0xFFFFFFFFu, vsq[k], 2);
        }
        if ((lane & 3) == 0) {
#pragma unroll
            for (int tm = 0; tm < 2; ++tm)
#pragma unroll
                for (int rh = 0; rh < 2; ++rh) {
                    int rloc = warpM * 32 + tm * 16 + rh * 8 + qrow;
                    atomicAdd(&rsum[rloc], vsum[tm * 2 + rh]);
                    atomicAdd(&rsq[rloc], vsq[tm * 2 + rh]);
                }
        }
        __syncthreads();
    }

#pragma unroll
    for (int tm = 0; tm < 2; ++tm) {
#pragma unroll
        for (int rh = 0; rh < 2; ++rh) {
            int rloc = warpM * 32 + tm * 16 + rh * 8 + qrow;
            int rg = row0 + rloc;
            if (rg >= M) continue;
            float mean = 0.f, inv = 1.f;
            if (MODE == 0) {
                mean = rsum[rloc] * (1.f / 256.f);
                inv = rsqrtf(rsq[rloc] * (1.f / 256.f) - mean * mean + 1e-5f);
            }
#pragma unroll
            for (int tn = 0; tn < 8; ++tn) {
                int c = warpN * 64 + tn * 8 + qc;
                float a0 = acc[tm][tn][rh * 2 + 0];
                float a1 = acc[tm][tn][rh * 2 + 1];
                if (MODE == 0) {
                    a0 = (a0 - mean) * inv * sgam[c] + sbet[c];
                    a1 = (a1 - mean) * inv * sgam[c + 1] + sbet[c + 1];
                    *(float2*)(outf + (size_t)rg * 256 + c) = make_float2(a0, a1);
                    if (outh != nullptr) {
                        uint32_t lw;
                        uint32_t hw = pack2hf(a0, a1, lw);
                        ((uint32_t*)outh)[((size_t)rg * 256 + c) >> 1] = hw;
                        ((uint32_t*)outl)[((size_t)rg * 256 + c) >> 1] = lw;
                    }
                } else {
                    uint32_t lw;
                    uint32_t hw = pack2hf(a0, a1, lw);
                    size_t off = ((size_t)rg * HF + col0 + c) >> 1;
                    ((uint32_t*)outh)[off] = hw;
                    ((uint32_t*)outl)[off] = lw;
                }
            }
        }
    }
}

// ------------------------------ launch --------------------------------------
extern "C" void kernel_launch(void* const* d_in, const int* in_sizes, int n_in,
                              void* d_out, int out_size) {
    const float* x      = (const float*)d_in[0];
    const int*   ei     = (const int*)d_in[1];
    const float* W_nbr  = (const float*)d_in[2];
    const float* W_root = (const float*)d_in[3];
    const float* b_gnn  = (const float*)d_in[4];
    const float* W1     = (const float*)d_in[5];
    const float* b1     = (const float*)d_in[6];
    const float* W2     = (const float*)d_in[7];
    const float* b2     = (const float*)d_in[8];
    const float* g1     = (const float*)d_in[9];
    const float* be1    = (const float*)d_in[10];
    const float* g2     = (const float*)d_in[11];
    const float* be2    = (const float*)d_in[12];
    float* out = (float*)d_out;

    const int M = in_sizes[0] / HD;
    const int E = in_sizes[1] / 2;

    float* h;
    __half *xh, *xl, *agh, *agl, *hh, *hl, *th, *tl;
    __half *wnh, *wrh, *w1h, *w2h;
    int *deg, *off, *cur, *srcl;
    cudaGetSymbolAddress((void**)&h, g_h);
    cudaGetSymbolAddress((void**)&xh, g_x_h);  cudaGetSymbolAddress((void**)&xl, g_x_l);
    cudaGetSymbolAddress((void**)&agh, g_ag_h); cudaGetSymbolAddress((void**)&agl, g_ag_l);
    cudaGetSymbolAddress((void**)&hh, g_h_h);  cudaGetSymbolAddress((void**)&hl, g_h_l);
    cudaGetSymbolAddress((void**)&th, g_t_h);  cudaGetSymbolAddress((void**)&tl, g_t_l);
    cudaGetSymbolAddress((void**)&wnh, g_wn_h);
    cudaGetSymbolAddress((void**)&wrh, g_wr_h);
    cudaGetSymbolAddress((void**)&w1h, g_w1_h);
    cudaGetSymbolAddress((void**)&w2h, g_w2_h);
    cudaGetSymbolAddress((void**)&deg, g_deg);
    cudaGetSymbolAddress((void**)&off, g_off);
    cudaGetSymbolAddress((void**)&cur, g_cur);
    cudaGetSymbolAddress((void**)&srcl, g_srcl);

    cudaFuncSetAttribute(gemm_mma<0>, cudaFuncAttributeMaxDynamicSharedMemorySize, SMEM_TOTAL);
    cudaFuncSetAttribute(gemm_mma<1>, cudaFuncAttributeMaxDynamicSharedMemorySize, SMEM_TOTAL);

    int n4 = M * HD / 4;
    // split x first (scatter/gather reads fp16 xh)
    split_kernel<<<(n4 + 255) / 256, 256>>>(x, xh, xl, n4);
    detect_kernel<<<1, 1>>>(ei, 2 * E);

    // CSR build + gather
    zero_deg_kernel<<<(M + 255) / 256, 256>>>(deg, M);
    hist_kernel<<<(E + 255) / 256, 256>>>(ei, E, deg);
    scan_kernel<<<1, 1024>>>(deg, off, cur, M);
    fill_kernel<<<(E + 255) / 256, 256>>>(ei, E, cur, srcl);
    gather_kernel<<<(M + 7) / 8, 256>>>(off, srcl, xh, agh, agl, M);

    tsplit_kernel<<<(HD * HD + 255) / 256, 256>>>(W_nbr, wnh, HD, HD);
    tsplit_kernel<<<(HD * HD + 255) / 256, 256>>>(W_root, wrh, HD, HD);
    tsplit_kernel<<<(HD * HF + 255) / 256, 256>>>(W1, w1h, HD, HF);
    tsplit_kernel<<<(HD * HF + 255) / 256, 256>>>(W2, w2h, HF, HD);

    int gx = (M + 63) / 64;

    // h = LN1(x + agg@Wnbr + x@Wroot + b_gnn), emit fp16 hi/lo of h
    gemm_mma<0><<<dim3(gx, 1), 256, SMEM_TOTAL>>>(
        agh, agl, wnh, HD, xh, xl, wrh, HD,
        b_gnn, x, g1, be1, h, hh, hl, M);

    // t = relu(h@W1 + b1) (fp16 hi/lo only)
    gemm_mma<1><<<dim3(gx, 2), 256, SMEM_TOTAL>>>(
        hh, hl, w1h, HD, nullptr, nullptr, nullptr, 0,
        b1, nullptr, nullptr, nullptr, nullptr, th, tl, M);

    // out = LN2(h + t@W2 + b2)
    gemm_mma<0><<<dim3(gx, 1), 256, SMEM_TOTAL>>>(
        th, tl, w2h, HF, nullptr, nullptr, nullptr, 0,
        b2, h, g2, be2, out, nullptr, nullptr, M);
}

// round 6
// speedup vs baseline: 3.1592x; 1.2836x over previous
#include <cuda_runtime.h>
#include <cuda_fp16.h>
#include <cstdint>

#define HD 256
#define HF 512
#define NMAX 50000
#define EMAX 800000

// ------------------------- scratch (device globals) ------------------------
__device__ float g_h[(size_t)NMAX * HD];
__device__ __half g_x_h[(size_t)NMAX * HD];
__device__ __half g_ag_h[(size_t)NMAX * HD];
__device__ __half g_h_h[(size_t)NMAX * HD];
__device__ __half g_t_h[(size_t)NMAX * HF];
__device__ __half g_wn_h[HD * HD];
__device__ __half g_wr_h[HD * HD];
__device__ __half g_w1_h[HD * HF];
__device__ __half g_w2_h[HD * HF];
__device__ int g_deg[NMAX];
__device__ int g_off[NMAX + 1];
__device__ int g_cur[NMAX];
__device__ int g_srcl[EMAX];
__device__ int g_is64;

// ----------------------------- helpers -------------------------------------
__device__ __forceinline__ uint32_t smem_u32(const void* p) {
    uint32_t a;
    asm("{ .reg .u64 t; cvta.to.shared.u64 t, %1; cvt.u32.u64 %0, t; }" : "=r"(a) : "l"(p));
    return a;
}
__device__ __forceinline__ void ldsm_x4(uint32_t* r, uint32_t addr) {
    asm volatile("ldmatrix.sync.aligned.m8n8.x4.shared.b16 {%0,%1,%2,%3}, [%4];"
                 : "=r"(r[0]), "=r"(r[1]), "=r"(r[2]), "=r"(r[3]) : "r"(addr));
}
__device__ __forceinline__ void ldsm_x2(uint32_t* r, uint32_t addr) {
    asm volatile("ldmatrix.sync.aligned.m8n8.x2.shared.b16 {%0,%1}, [%2];"
                 : "=r"(r[0]), "=r"(r[1]) : "r"(addr));
}
__device__ __forceinline__ void mma_f16(float* d, const uint32_t* a, const uint32_t* b) {
    asm volatile(
        "mma.sync.aligned.m16n8k16.row.col.f32.f16.f16.f32 "
        "{%0,%1,%2,%3}, {%4,%5,%6,%7}, {%8,%9}, {%0,%1,%2,%3};"
        : "+f"(d[0]), "+f"(d[1]), "+f"(d[2]), "+f"(d[3])
        : "r"(a[0]), "r"(a[1]), "r"(a[2]), "r"(a[3]), "r"(b[0]), "r"(b[1]));
}
__device__ __forceinline__ void cp_async16(uint32_t dst, const void* src, int szr) {
    asm volatile("cp.async.cg.shared.global [%0], [%1], 16, %2;"
                 :: "r"(dst), "l"(src), "r"(szr) : "memory");
}
#define CP_COMMIT() asm volatile("cp.async.commit_group;" ::: "memory")
#define CP_WAIT2()  asm volatile("cp.async.wait_group 2;" ::: "memory")
#define CP_WAIT0()  asm volatile("cp.async.wait_group 0;" ::: "memory")

__device__ __forceinline__ uint32_t packh2(float a, float b) {
    __half2 h = __float22half2_rn(make_float2(a, b));
    return *(uint32_t*)&h;
}

// --------------------------- small kernels ---------------------------------
__global__ void detect_kernel(const int* __restrict__ ei, int twoE) {
    int nz = 0;
    int lim = twoE * 2;
    if (lim > 256) lim = 256;
    for (int i = 1; i < lim; i += 2) nz |= ei[i];
    g_is64 = (nz == 0) ? 1 : 0;
}

__global__ void zero_deg_kernel(int* __restrict__ deg, int M) {
    int i = blockIdx.x * blockDim.x + threadIdx.x;
    if (i < M) deg[i] = 0;
}

__global__ void hist_kernel(const int* __restrict__ ei, int E, int* __restrict__ deg) {
    int e = blockIdx.x * blockDim.x + threadIdx.x;
    if (e >= E) return;
    int d = g_is64 ? ei[2 * (E + e)] : ei[E + e];
    atomicAdd(&deg[d], 1);
}

// hierarchical exclusive scan over degrees, one block of 1024
__global__ void scan_kernel(const int* __restrict__ deg, int* __restrict__ off,
                            int* __restrict__ cur, int M) {
    __shared__ int wsum[32];
    const int t = threadIdx.x;
    const int lane = t & 31, wid = t >> 5;
    const int chunk = (M + 1023) / 1024;
    int c0 = t * chunk, c1 = min(c0 + chunk, M);
    int s = 0;
    for (int i = c0; i < c1; ++i) s += deg[i];
    int v = s;
#pragma unroll
    for (int o = 1; o < 32; o <<= 1) {
        int u = __shfl_up_sync(0xFFFFFFFFu, v, o);
        if (lane >= o) v += u;
    }
    if (lane == 31) wsum[wid] = v;
    __syncthreads();
    if (wid == 0) {
        int w = wsum[lane];
#pragma unroll
        for (int o = 1; o < 32; o <<= 1) {
            int u = __shfl_up_sync(0xFFFFFFFFu, w, o);
            if (lane >= o) w += u;
        }
        wsum[lane] = w;
    }
    __syncthreads();
    int run = v - s + (wid ? wsum[wid - 1] : 0);
    for (int i = c0; i < c1; ++i) {
        off[i] = run; cur[i] = run; run += deg[i];
    }
    if (t == 1023) off[M] = run;
}

__global__ void fill_kernel(const int* __restrict__ ei, int E,
                            int* __restrict__ cur, int* __restrict__ srcl) {
    int e = blockIdx.x * blockDim.x + threadIdx.x;
    if (e >= E) return;
    int s, d;
    if (g_is64) { s = ei[2 * e]; d = ei[2 * (E + e)]; }
    else        { s = ei[e];     d = ei[E + e]; }
    int pos = atomicAdd(&cur[d], 1);
    srcl[pos] = s;
}

// gather: one warp per node; unroll-8 neighbor batches; emit fp16 agg
__global__ void __launch_bounds__(256)
gather_kernel(const int* __restrict__ off, const int* __restrict__ srcl,
              const __half* __restrict__ xh, __half* __restrict__ agh, int M) {
    int node = blockIdx.x * 8 + (threadIdx.x >> 5);
    int lane = threadIdx.x & 31;
    if (node >= M) return;
    int j0 = off[node], j1 = off[node + 1];

    float acc[8];
#pragma unroll
    for (int k = 0; k < 8; ++k) acc[k] = 0.f;

    const uint4* xb = (const uint4*)xh;
    int j = j0;
    for (; j + 8 <= j1; j += 8) {
        int srcs[8];
#pragma unroll
        for (int u = 0; u < 8; ++u) srcs[u] = srcl[j + u];
        uint4 v[8];
#pragma unroll
        for (int u = 0; u < 8; ++u) v[u] = xb[(size_t)srcs[u] * 32 + lane];
#pragma unroll
        for (int u = 0; u < 8; ++u) {
            float2 f0 = __half22float2(*(const __half2*)&v[u].x);
            float2 f1 = __half22float2(*(const __half2*)&v[u].y);
            float2 f2 = __half22float2(*(const __half2*)&v[u].z);
            float2 f3 = __half22float2(*(const __half2*)&v[u].w);
            acc[0] += f0.x; acc[1] += f0.y; acc[2] += f1.x; acc[3] += f1.y;
            acc[4] += f2.x; acc[5] += f2.y; acc[6] += f3.x; acc[7] += f3.y;
        }
    }
    for (; j < j1; ++j) {
        uint4 v = xb[(size_t)srcl[j] * 32 + lane];
        float2 f0 = __half22float2(*(const __half2*)&v.x);
        float2 f1 = __half22float2(*(const __half2*)&v.y);
        float2 f2 = __half22float2(*(const __half2*)&v.z);
        float2 f3 = __half22float2(*(const __half2*)&v.w);
        acc[0] += f0.x; acc[1] += f0.y; acc[2] += f1.x; acc[3] += f1.y;
        acc[4] += f2.x; acc[5] += f2.y; acc[6] += f3.x; acc[7] += f3.y;
    }

    uint32_t hi[4];
#pragma unroll
    for (int k = 0; k < 4; ++k) hi[k] = packh2(acc[2 * k], acc[2 * k + 1]);
    ((uint4*)agh)[(size_t)node * 32 + lane] = make_uint4(hi[0], hi[1], hi[2], hi[3]);
}

__global__ void conv_kernel(const float* __restrict__ in,
                            __half* __restrict__ oh, int n4) {
    int i = blockIdx.x * blockDim.x + threadIdx.x;
    if (i >= n4) return;
    float4 v = ((const float4*)in)[i];
    ((uint2*)oh)[i] = make_uint2(packh2(v.x, v.y), packh2(v.z, v.w));
}

// W [K,N] -> out [N,K] fp16
__global__ void tsplit_kernel(const float* __restrict__ W,
                              __half* __restrict__ oh, int K, int N) {
    int idx = blockIdx.x * blockDim.x + threadIdx.x;
    if (idx >= K * N) return;
    int n = idx / K, k = idx - n * K;
    oh[idx] = __float2half_rn(W[(size_t)k * N + n]);
}

// ----------------------- fp16 single-term mma.sync GEMM --------------------
// BM=64, BN=256, BK=32, 256 threads, 4-stage cp.async pipeline, 2 CTAs/SM.
// stage: A 64 rows x 80B = 5120B, B 256 rows x 80B = 20480B
#define STAGE_BYTES 25600
#define NSTAGE 4
#define SMEM_TOTAL (NSTAGE * STAGE_BYTES)

__device__ __forceinline__ void load_stage(
    uint32_t sa, int tid, int row0, int col0,
    const __half* A, const __half* B, int K, int kc, int M) {
    {   // A: 256 chunks of 16B
        int r = tid >> 2, c = tid & 3;
        int row = row0 + r;
        int szr = (row < M) ? 16 : 0;
        size_t roff = (row < M) ? (size_t)row : 0;
        cp_async16(sa + r * 80 + c * 16, A + roff * K + kc + c * 8, szr);
    }
    uint32_t sb = sa + 5120;
#pragma unroll
    for (int j = 0; j < 4; ++j) {   // B: 1024 chunks
        int id = tid + j * 256;
        int r = id >> 2, c = id & 3;
        cp_async16(sb + r * 80 + c * 16, B + (size_t)(col0 + r) * K + kc + c * 8, 16);
    }
}

// MODE 0: C = A@B(+A1@B1) + bias + resid -> LN(gamma,beta) -> outf (+opt fp16)
// MODE 1: C = relu(A@B + bias) -> fp16 out only (stride HF)
template <int MODE>
__global__ void __launch_bounds__(256, 2)
gemm_mma(const __half* __restrict__ A0, const __half* __restrict__ B0, int K0,
         const __half* __restrict__ A1, const __half* __restrict__ B1, int K1,
         const float* __restrict__ bias, const float* __restrict__ resid,
         const float* __restrict__ gamma, const float* __restrict__ beta,
         float* __restrict__ outf, __half* __restrict__ outh, int M) {
    extern __shared__ char smem[];
    const uint32_t sb0 = smem_u32(smem);
    const int tid = threadIdx.x;
    const int lane = tid & 31;
    const int warp = tid >> 5;
    const int warpM = warp >> 2;
    const int warpN = warp & 3;
    const int row0 = blockIdx.x * 64;
    const int col0 = blockIdx.y * 256;

    float acc[2][8][4];
#pragma unroll
    for (int i = 0; i < 2; ++i)
#pragma unroll
        for (int j = 0; j < 8; ++j)
#pragma unroll
            for (int k = 0; k < 4; ++k) acc[i][j][k] = 0.f;

    const int S = (K0 + K1) >> 5;

    const uint32_t aoff = (uint32_t)((warpM * 32 + (lane & 7) + ((lane >> 3) & 1) * 8) * 80
                                     + (lane >> 4) * 16);
    const uint32_t boff = (uint32_t)((warpN * 64 + (lane & 7)) * 80 + ((lane >> 3) & 1) * 16);

#define RESOLVE(IT, AH, BH, KK, KC)                             \
    { int kt = (IT) * 32;                                       \
      if (kt < K0) { AH = A0; BH = B0; KK = K0; KC = kt; }      \
      else         { AH = A1; BH = B1; KK = K1; KC = kt - K0; } }

    // prologue: stages 0..2
#pragma unroll
    for (int p = 0; p < NSTAGE - 1; ++p) {
        if (p < S) {
            const __half *Ah, *Bh; int KK, KC;
            RESOLVE(p, Ah, Bh, KK, KC);
            load_stage(sb0 + p * STAGE_BYTES, tid, row0, col0, Ah, Bh, KK, KC, M);
        }
        CP_COMMIT();
    }

    int stage = 0;
    for (int it = 0; it < S; ++it) {
        CP_WAIT2();
        __syncthreads();
        if (it + NSTAGE - 1 < S) {
            int s2 = stage + NSTAGE - 1; if (s2 >= NSTAGE) s2 -= NSTAGE;
            const __half *Ah, *Bh; int KK, KC;
            RESOLVE(it + NSTAGE - 1, Ah, Bh, KK, KC);
            load_stage(sb0 + s2 * STAGE_BYTES, tid, row0, col0, Ah, Bh, KK, KC, M);
        }
        CP_COMMIT();

        const uint32_t sa = sb0 + stage * STAGE_BYTES;
        const uint32_t sbB = sa + 5120;
#pragma unroll
        for (int ks = 0; ks < 2; ++ks) {
            uint32_t ah[2][4];
#pragma unroll
            for (int tm = 0; tm < 2; ++tm)
                ldsm_x4(ah[tm], sa + aoff + tm * 1280 + ks * 32);
#pragma unroll
            for (int tn = 0; tn < 8; ++tn) {
                uint32_t bh[2];
                ldsm_x2(bh, sbB + boff + tn * 640 + ks * 32);
#pragma unroll
                for (int tm = 0; tm < 2; ++tm)
                    mma_f16(acc[tm][tn], ah[tm], bh);
            }
        }
        ++stage; if (stage == NSTAGE) stage = 0;
    }

    CP_WAIT0();
    __syncthreads();

    // ---------------------------- epilogue ---------------------------------
    float* rsum  = (float*)smem;
    float* rsq   = rsum + 64;
    float* sbias = rsq + 64;
    float* sgam  = sbias + 256;
    float* sbet  = sgam + 256;
    if (MODE == 0 && tid < 64) { rsum[tid] = 0.f; rsq[tid] = 0.f; }
    sbias[tid] = bias[col0 + tid];
    if (MODE == 0) { sgam[tid] = gamma[tid]; sbet[tid] = beta[tid]; }
    __syncthreads();

    const int qrow = lane >> 2;
    const int qc = (lane & 3) * 2;

    float vsum[4], vsq[4];
#pragma unroll
    for (int k = 0; k < 4; ++k) { vsum[k] = 0.f; vsq[k] = 0.f; }

#pragma unroll
    for (int tm = 0; tm < 2; ++tm) {
#pragma unroll
        for (int rh = 0; rh < 2; ++rh) {
            int rloc = warpM * 32 + tm * 16 + rh * 8 + qrow;
            int rg = row0 + rloc;
            bool v = rg < M;
#pragma unroll
            for (int tn = 0; tn < 8; ++tn) {
                int c = warpN * 64 + tn * 8 + qc;
                float a0 = acc[tm][tn][rh * 2 + 0] + sbias[c];
                float a1 = acc[tm][tn][rh * 2 + 1] + sbias[c + 1];
                if (MODE == 0) {
                    if (v) {
                        float2 q = *(const float2*)(resid + (size_t)rg * 256 + c);
                        a0 += q.x; a1 += q.y;
                    }
                    vsum[tm * 2 + rh] += a0 + a1;
                    vsq[tm * 2 + rh] += a0 * a0 + a1 * a1;
                } else {
                    a0 = fmaxf(a0, 0.f); a1 = fmaxf(a1, 0.f);
                }
                acc[tm][tn][rh * 2 + 0] = a0;
                acc[tm][tn][rh * 2 + 1] = a1;
            }
        }
    }

    if (MODE == 0) {
#pragma unroll
        for (int k = 0; k < 4; ++k) {
            vsum[k] += __shfl_xor_sync(0xFFFFFFFFu, vsum[k], 1);
            vsum[k] += __shfl_xor_sync(0xFFFFFFFFu, vsum[k], 2);
            vsq[k]  += __shfl_xor_sync(0xFFFFFFFFu, vsq[k], 1);
            vsq[k]  += __shfl_xor_sync(0xFFFFFFFFu, vsq[k], 2);
        }
        if ((lane & 3) == 0) {
#pragma unroll
            for (int tm = 0; tm < 2; ++tm)
#pragma unroll
                for (int rh = 0; rh < 2; ++rh) {
                    int rloc = warpM * 32 + tm * 16 + rh * 8 + qrow;
                    atomicAdd(&rsum[rloc], vsum[tm * 2 + rh]);
                    atomicAdd(&rsq[rloc], vsq[tm * 2 + rh]);
                }
        }
        __syncthreads();
    }

#pragma unroll
    for (int tm = 0; tm < 2; ++tm) {
#pragma unroll
        for (int rh = 0; rh < 2; ++rh) {
            int rloc = warpM * 32 + tm * 16 + rh * 8 + qrow;
            int rg = row0 + rloc;
            if (rg >= M) continue;
            float mean = 0.f, inv = 1.f;
            if (MODE == 0) {
                mean = rsum[rloc] * (1.f / 256.f);
                inv = rsqrtf(rsq[rloc] * (1.f / 256.f) - mean * mean + 1e-5f);
            }
#pragma unroll
            for (int tn = 0; tn < 8; ++tn) {
                int c = warpN * 64 + tn * 8 + qc;
                float a0 = acc[tm][tn][rh * 2 + 0];
                float a1 = acc[tm][tn][rh * 2 + 1];
                if (MODE == 0) {
                    a0 = (a0 - mean) * inv * sgam[c] + sbet[c];
                    a1 = (a1 - mean) * inv * sgam[c + 1] + sbet[c + 1];
                    *(float2*)(outf + (size_t)rg * 256 + c) = make_float2(a0, a1);
                    if (outh != nullptr)
                        ((uint32_t*)outh)[((size_t)rg * 256 + c) >> 1] = packh2(a0, a1);
                } else {
                    ((uint32_t*)outh)[((size_t)rg * HF + col0 + c) >> 1] = packh2(a0, a1);
                }
            }
        }
    }
}

// ------------------------------ launch --------------------------------------
extern "C" void kernel_launch(void* const* d_in, const int* in_sizes, int n_in,
                              void* d_out, int out_size) {
    const float* x      = (const float*)d_in[0];
    const int*   ei     = (const int*)d_in[1];
    const float* W_nbr  = (const float*)d_in[2];
    const float* W_root = (const float*)d_in[3];
    const float* b_gnn  = (const float*)d_in[4];
    const float* W1     = (const float*)d_in[5];
    const float* b1     = (const float*)d_in[6];
    const float* W2     = (const float*)d_in[7];
    const float* b2     = (const float*)d_in[8];
    const float* g1     = (const float*)d_in[9];
    const float* be1    = (const float*)d_in[10];
    const float* g2     = (const float*)d_in[11];
    const float* be2    = (const float*)d_in[12];
    float* out = (float*)d_out;

    const int M = in_sizes[0] / HD;
    const int E = in_sizes[1] / 2;

    float* h;
    __half *xh, *agh, *hh, *th, *wnh, *wrh, *w1h, *w2h;
    int *deg, *off, *cur, *srcl;
    cudaGetSymbolAddress((void**)&h, g_h);
    cudaGetSymbolAddress((void**)&xh, g_x_h);
    cudaGetSymbolAddress((void**)&agh, g_ag_h);
    cudaGetSymbolAddress((void**)&hh, g_h_h);
    cudaGetSymbolAddress((void**)&th, g_t_h);
    cudaGetSymbolAddress((void**)&wnh, g_wn_h);
    cudaGetSymbolAddress((void**)&wrh, g_wr_h);
    cudaGetSymbolAddress((void**)&w1h, g_w1_h);
    cudaGetSymbolAddress((void**)&w2h, g_w2_h);
    cudaGetSymbolAddress((void**)&deg, g_deg);
    cudaGetSymbolAddress((void**)&off, g_off);
    cudaGetSymbolAddress((void**)&cur, g_cur);
    cudaGetSymbolAddress((void**)&srcl, g_srcl);

    cudaFuncSetAttribute(gemm_mma<0>, cudaFuncAttributeMaxDynamicSharedMemorySize, SMEM_TOTAL);
    cudaFuncSetAttribute(gemm_mma<1>, cudaFuncAttributeMaxDynamicSharedMemorySize, SMEM_TOTAL);

    int n4 = M * HD / 4;
    conv_kernel<<<(n4 + 255) / 256, 256>>>(x, xh, n4);
    detect_kernel<<<1, 1>>>(ei, 2 * E);

    zero_deg_kernel<<<(M + 255) / 256, 256>>>(deg, M);
    hist_kernel<<<(E + 255) / 256, 256>>>(ei, E, deg);
    scan_kernel<<<1, 1024>>>(deg, off, cur, M);
    fill_kernel<<<(E + 255) / 256, 256>>>(ei, E, cur, srcl);
    gather_kernel<<<(M + 7) / 8, 256>>>(off, srcl, xh, agh, M);

    tsplit_kernel<<<(HD * HD + 255) / 256, 256>>>(W_nbr, wnh, HD, HD);
    tsplit_kernel<<<(HD * HD + 255) / 256, 256>>>(W_root, wrh, HD, HD);
    tsplit_kernel<<<(HD * HF + 255) / 256, 256>>>(W1, w1h, HD, HF);
    tsplit_kernel<<<(HD * HF + 255) / 256, 256>>>(W2, w2h, HF, HD);

    int gx = (M + 63) / 64;

    // h = LN1(x + agg@Wnbr + x@Wroot + b_gnn), emit fp16 of h
    gemm_mma<0><<<dim3(gx, 1), 256, SMEM_TOTAL>>>(
        agh, wnh, HD, xh, wrh, HD, b_gnn, x, g1, be1, h, hh, M);

    // t = relu(h@W1 + b1) (fp16 only)
    gemm_mma<1><<<dim3(gx, 2), 256, SMEM_TOTAL>>>(
        hh, w1h, HD, nullptr, nullptr, 0,
        b1, nullptr, nullptr, nullptr, nullptr, th, M);

    // out = LN2(h + t@W2 + b2)
    gemm_mma<0><<<dim3(gx, 1), 256, SMEM_TOTAL>>>(
        th, w2h, HF, nullptr, nullptr, 0,
        b2, h, g2, be2, out, nullptr, M);
}

// round 7
// speedup vs baseline: 3.2219x; 1.0198x over previous
#include <cuda_runtime.h>
#include <cuda_fp16.h>
#include <cstdint>

#define HD 256
#define HF 512
#define NMAX 50000
#define EMAX 800000

// ------------------------- scratch (device globals) ------------------------
__device__ float g_h[(size_t)NMAX * HD];
__device__ __half g_x_h[(size_t)NMAX * HD];
__device__ __half g_ag_h[(size_t)NMAX * HD];
__device__ __half g_h_h[(size_t)NMAX * HD];
__device__ __half g_t_h[(size_t)NMAX * HF];
__device__ __half g_wn_h[HD * HD];
__device__ __half g_wr_h[HD * HD];
__device__ __half g_w1_h[HD * HF];
__device__ __half g_w2_h[HD * HF];
__device__ int g_deg[NMAX];
__device__ int g_off[NMAX + 1];
__device__ int g_cur[NMAX];
__device__ int g_srcl[EMAX];
__device__ int g_is64;

// ----------------------------- helpers -------------------------------------
__device__ __forceinline__ uint32_t smem_u32(const void* p) {
    uint32_t a;
    asm("{ .reg .u64 t; cvta.to.shared.u64 t, %1; cvt.u32.u64 %0, t; }" : "=r"(a) : "l"(p));
    return a;
}
__device__ __forceinline__ void ldsm_x4(uint32_t* r, uint32_t addr) {
    asm volatile("ldmatrix.sync.aligned.m8n8.x4.shared.b16 {%0,%1,%2,%3}, [%4];"
                 : "=r"(r[0]), "=r"(r[1]), "=r"(r[2]), "=r"(r[3]) : "r"(addr));
}
__device__ __forceinline__ void mma_f16(float* d, const uint32_t* a, const uint32_t* b) {
    asm volatile(
        "mma.sync.aligned.m16n8k16.row.col.f32.f16.f16.f32 "
        "{%0,%1,%2,%3}, {%4,%5,%6,%7}, {%8,%9}, {%0,%1,%2,%3};"
        : "+f"(d[0]), "+f"(d[1]), "+f"(d[2]), "+f"(d[3])
        : "r"(a[0]), "r"(a[1]), "r"(a[2]), "r"(a[3]), "r"(b[0]), "r"(b[1]));
}
__device__ __forceinline__ void cp_async16(uint32_t dst, const void* src, int szr) {
    asm volatile("cp.async.cg.shared.global [%0], [%1], 16, %2;"
                 :: "r"(dst), "l"(src), "r"(szr) : "memory");
}
#define CP_COMMIT() asm volatile("cp.async.commit_group;" ::: "memory")
#define CP_WAIT2()  asm volatile("cp.async.wait_group 2;" ::: "memory")
#define CP_WAIT0()  asm volatile("cp.async.wait_group 0;" ::: "memory")

__device__ __forceinline__ uint32_t packh2(float a, float b) {
    __half2 h = __float22half2_rn(make_float2(a, b));
    return *(uint32_t*)&h;
}

// --------------------------- small kernels ---------------------------------
__global__ void detect_kernel(const int* __restrict__ ei, int twoE) {
    int nz = 0;
    int lim = twoE * 2;
    if (lim > 256) lim = 256;
    for (int i = 1; i < lim; i += 2) nz |= ei[i];
    g_is64 = (nz == 0) ? 1 : 0;
}

// vectorized histogram: int32 path 4 edges/thread, int64 path 2 edges/thread
__global__ void hist_kernel(const int* __restrict__ ei, int E, int* __restrict__ deg) {
    int t = blockIdx.x * blockDim.x + threadIdx.x;
    if (g_is64) {
        int e0 = t * 2;
        if (e0 >= E) return;
        if (e0 + 2 <= E) {
            int4 d = *(const int4*)(ei + 2 * (E + e0));
            atomicAdd(&deg[d.x], 1);
            atomicAdd(&deg[d.z], 1);
        } else {
            atomicAdd(&deg[ei[2 * (E + e0)]], 1);
        }
    } else {
        int e0 = t * 4;
        if (e0 >= E) return;
        if (e0 + 4 <= E) {
            int4 d = *(const int4*)(ei + E + e0);
            atomicAdd(&deg[d.x], 1);
            atomicAdd(&deg[d.y], 1);
            atomicAdd(&deg[d.z], 1);
            atomicAdd(&deg[d.w], 1);
        } else {
            for (int e = e0; e < E; ++e) atomicAdd(&deg[ei[E + e]], 1);
        }
    }
}

// hierarchical exclusive scan over degrees, one block of 1024
__global__ void scan_kernel(const int* __restrict__ deg, int* __restrict__ off,
                            int* __restrict__ cur, int M) {
    __shared__ int wsum[32];
    const int t = threadIdx.x;
    const int lane = t & 31, wid = t >> 5;
    const int chunk = (M + 1023) / 1024;
    int c0 = t * chunk, c1 = min(c0 + chunk, M);
    int s = 0;
    for (int i = c0; i < c1; ++i) s += deg[i];
    int v = s;
#pragma unroll
    for (int o = 1; o < 32; o <<= 1) {
        int u = __shfl_up_sync(0xFFFFFFFFu, v, o);
        if (lane >= o) v += u;
    }
    if (lane == 31) wsum[wid] = v;
    __syncthreads();
    if (wid == 0) {
        int w = wsum[lane];
#pragma unroll
        for (int o = 1; o < 32; o <<= 1) {
            int u = __shfl_up_sync(0xFFFFFFFFu, w, o);
            if (lane >= o) w += u;
        }
        wsum[lane] = w;
    }
    __syncthreads();
    int run = v - s + (wid ? wsum[wid - 1] : 0);
    for (int i = c0; i < c1; ++i) {
        off[i] = run; cur[i] = run; run += deg[i];
    }
    if (t == 1023) off[M] = run;
}

__global__ void fill_kernel(const int* __restrict__ ei, int E,
                            int* __restrict__ cur, int* __restrict__ srcl) {
    int t = blockIdx.x * blockDim.x + threadIdx.x;
    if (g_is64) {
        int e0 = t * 2;
        if (e0 >= E) return;
        if (e0 + 2 <= E) {
            int4 s = *(const int4*)(ei + 2 * e0);
            int4 d = *(const int4*)(ei + 2 * (E + e0));
            srcl[atomicAdd(&cur[d.x], 1)] = s.x;
            srcl[atomicAdd(&cur[d.z], 1)] = s.z;
        } else {
            srcl[atomicAdd(&cur[ei[2 * (E + e0)]], 1)] = ei[2 * e0];
        }
    } else {
        int e0 = t * 4;
        if (e0 >= E) return;
        if (e0 + 4 <= E) {
            int4 s = *(const int4*)(ei + e0);
            int4 d = *(const int4*)(ei + E + e0);
            srcl[atomicAdd(&cur[d.x], 1)] = s.x;
            srcl[atomicAdd(&cur[d.y], 1)] = s.y;
            srcl[atomicAdd(&cur[d.z], 1)] = s.z;
            srcl[atomicAdd(&cur[d.w], 1)] = s.w;
        } else {
            for (int e = e0; e < E; ++e)
                srcl[atomicAdd(&cur[ei[E + e]], 1)] = ei[e];
        }
    }
}

// gather: one warp per node; unroll-8 neighbor batches; emit fp16 agg
__global__ void __launch_bounds__(256)
gather_kernel(const int* __restrict__ off, const int* __restrict__ srcl,
              const __half* __restrict__ xh, __half* __restrict__ agh, int M) {
    int node = blockIdx.x * 8 + (threadIdx.x >> 5);
    int lane = threadIdx.x & 31;
    if (node >= M) return;
    int j0 = off[node], j1 = off[node + 1];

    float acc[8];
#pragma unroll
    for (int k = 0; k < 8; ++k) acc[k] = 0.f;

    const uint4* xb = (const uint4*)xh;
    int j = j0;
    for (; j + 8 <= j1; j += 8) {
        int srcs[8];
#pragma unroll
        for (int u = 0; u < 8; ++u) srcs[u] = srcl[j + u];
        uint4 v[8];
#pragma unroll
        for (int u = 0; u < 8; ++u) v[u] = xb[(size_t)srcs[u] * 32 + lane];
#pragma unroll
        for (int u = 0; u < 8; ++u) {
            float2 f0 = __half22float2(*(const __half2*)&v[u].x);
            float2 f1 = __half22float2(*(const __half2*)&v[u].y);
            float2 f2 = __half22float2(*(const __half2*)&v[u].z);
            float2 f3 = __half22float2(*(const __half2*)&v[u].w);
            acc[0] += f0.x; acc[1] += f0.y; acc[2] += f1.x; acc[3] += f1.y;
            acc[4] += f2.x; acc[5] += f2.y; acc[6] += f3.x; acc[7] += f3.y;
        }
    }
    for (; j < j1; ++j) {
        uint4 v = xb[(size_t)srcl[j] * 32 + lane];
        float2 f0 = __half22float2(*(const __half2*)&v.x);
        float2 f1 = __half22float2(*(const __half2*)&v.y);
        float2 f2 = __half22float2(*(const __half2*)&v.z);
        float2 f3 = __half22float2(*(const __half2*)&v.w);
        acc[0] += f0.x; acc[1] += f0.y; acc[2] += f1.x; acc[3] += f1.y;
        acc[4] += f2.x; acc[5] += f2.y; acc[6] += f3.x; acc[7] += f3.y;
    }

    uint32_t hi[4];
#pragma unroll
    for (int k = 0; k < 4; ++k) hi[k] = packh2(acc[2 * k], acc[2 * k + 1]);
    ((uint4*)agh)[(size_t)node * 32 + lane] = make_uint4(hi[0], hi[1], hi[2], hi[3]);
}

__global__ void conv_kernel(const float* __restrict__ in,
                            __half* __restrict__ oh, int n4) {
    int i = blockIdx.x * blockDim.x + threadIdx.x;
    if (i >= n4) return;
    float4 v = ((const float4*)in)[i];
    ((uint2*)oh)[i] = make_uint2(packh2(v.x, v.y), packh2(v.z, v.w));
}

// tiled transpose: W [K,N] fp32 -> out [N,K] fp16, coalesced both sides
__global__ void ttrans_kernel(const float* __restrict__ W,
                              __half* __restrict__ out, int K, int N) {
    __shared__ float tile[32][33];
    int k0 = blockIdx.x * 32;
    int n0 = blockIdx.y * 32;
    int tx = threadIdx.x, ty = threadIdx.y;   // 32 x 8
#pragma unroll
    for (int i = 0; i < 4; ++i)
        tile[ty + i * 8][tx] = W[(size_t)(k0 + ty + i * 8) * N + n0 + tx];
    __syncthreads();
#pragma unroll
    for (int i = 0; i < 4; ++i)
        out[(size_t)(n0 + ty + i * 8) * K + k0 + tx] =
            __float2half_rn(tile[tx][ty + i * 8]);
}

// ----------------------- fp16 single-term mma.sync GEMM --------------------
// BM=64, BN=256, BK=32, 256 threads, 4-stage cp.async pipeline, 2 CTAs/SM.
#define STAGE_BYTES 25600
#define NSTAGE 4
#define SMEM_TOTAL (NSTAGE * STAGE_BYTES)

__device__ __forceinline__ void load_stage(
    uint32_t sa, int tid, int row0, int col0,
    const __half* A, const __half* B, int K, int kc, int M) {
    {
        int r = tid >> 2, c = tid & 3;
        int row = row0 + r;
        int szr = (row < M) ? 16 : 0;
        size_t roff = (row < M) ? (size_t)row : 0;
        cp_async16(sa + r * 80 + c * 16, A + roff * K + kc + c * 8, szr);
    }
    uint32_t sb = sa + 5120;
#pragma unroll
    for (int j = 0; j < 4; ++j) {
        int id = tid + j * 256;
        int r = id >> 2, c = id & 3;
        cp_async16(sb + r * 80 + c * 16, B + (size_t)(col0 + r) * K + kc + c * 8, 16);
    }
}

template <int MODE>
__global__ void __launch_bounds__(256, 2)
gemm_mma(const __half* __restrict__ A0, const __half* __restrict__ B0, int K0,
         const __half* __restrict__ A1, const __half* __restrict__ B1, int K1,
         const float* __restrict__ bias, const float* __restrict__ resid,
         const float* __restrict__ gamma, const float* __restrict__ beta,
         float* __restrict__ outf, __half* __restrict__ outh, int M) {
    extern __shared__ char smem[];
    const uint32_t sb0 = smem_u32(smem);
    const int tid = threadIdx.x;
    const int lane = tid & 31;
    const int warp = tid >> 5;
    const int warpM = warp >> 2;
    const int warpN = warp & 3;
    const int row0 = blockIdx.x * 64;
    const int col0 = blockIdx.y * 256;

    float acc[2][8][4];
#pragma unroll
    for (int i = 0; i < 2; ++i)
#pragma unroll
        for (int j = 0; j < 8; ++j)
#pragma unroll
            for (int k = 0; k < 4; ++k) acc[i][j][k] = 0.f;

    const int S = (K0 + K1) >> 5;

    const uint32_t aoff = (uint32_t)((warpM * 32 + (lane & 7) + ((lane >> 3) & 1) * 8) * 80
                                     + (lane >> 4) * 16);
    // B ldsm_x4: lanes 0-15 -> rows tn*8..+7 (k halves), lanes 16-31 -> rows (tn+1)*8..+7
    const uint32_t boff4 = (uint32_t)((warpN * 64 + (lane & 7) + (lane >> 4) * 8) * 80
                                      + ((lane >> 3) & 1) * 16);

#define RESOLVE(IT, AH, BH, KK, KC)                             \
    { int kt = (IT) * 32;                                       \
      if (kt < K0) { AH = A0; BH = B0; KK = K0; KC = kt; }      \
      else         { AH = A1; BH = B1; KK = K1; KC = kt - K0; } }

#pragma unroll
    for (int p = 0; p < NSTAGE - 1; ++p) {
        if (p < S) {
            const __half *Ah, *Bh; int KK, KC;
            RESOLVE(p, Ah, Bh, KK, KC);
            load_stage(sb0 + p * STAGE_BYTES, tid, row0, col0, Ah, Bh, KK, KC, M);
        }
        CP_COMMIT();
    }

    int stage = 0;
    for (int it = 0; it < S; ++it) {
        CP_WAIT2();
        __syncthreads();
        if (it + NSTAGE - 1 < S) {
            int s2 = stage + NSTAGE - 1; if (s2 >= NSTAGE) s2 -= NSTAGE;
            const __half *Ah, *Bh; int KK, KC;
            RESOLVE(it + NSTAGE - 1, Ah, Bh, KK, KC);
            load_stage(sb0 + s2 * STAGE_BYTES, tid, row0, col0, Ah, Bh, KK, KC, M);
        }
        CP_COMMIT();

        const uint32_t sa = sb0 + stage * STAGE_BYTES;
        const uint32_t sbB = sa + 5120;
#pragma unroll
        for (int ks = 0; ks < 2; ++ks) {
            uint32_t ah[2][4];
#pragma unroll
            for (int tm = 0; tm < 2; ++tm)
                ldsm_x4(ah[tm], sa + aoff + tm * 1280 + ks * 32);
#pragma unroll
            for (int tnp = 0; tnp < 4; ++tnp) {
                uint32_t bh[4];
                ldsm_x4(bh, sbB + boff4 + tnp * 1280 + ks * 32);
#pragma unroll
                for (int tm = 0; tm < 2; ++tm) {
                    mma_f16(acc[tm][2 * tnp + 0], ah[tm], bh);
                    mma_f16(acc[tm][2 * tnp + 1], ah[tm], bh + 2);
                }
            }
        }
        ++stage; if (stage == NSTAGE) stage = 0;
    }

    CP_WAIT0();
    __syncthreads();

    // ---------------------------- epilogue ---------------------------------
    float* rsum  = (float*)smem;
    float* rsq   = rsum + 64;
    float* sbias = rsq + 64;
    float* sgam  = sbias + 256;
    float* sbet  = sgam + 256;
    if (MODE == 0 && tid < 64) { rsum[tid] = 0.f; rsq[tid] = 0.f; }
    sbias[tid] = bias[col0 + tid];
    if (MODE == 0) { sgam[tid] = gamma[tid]; sbet[tid] = beta[tid]; }
    __syncthreads();

    const int qrow = lane >> 2;
    const int qc = (lane & 3) * 2;

    float vsum[4], vsq[4];
#pragma unroll
    for (int k = 0; k < 4; ++k) { vsum[k] = 0.f; vsq[k] = 0.f; }

#pragma unroll
    for (int tm = 0; tm < 2; ++tm) {
#pragma unroll
        for (int rh = 0; rh < 2; ++rh) {
            int rloc = warpM * 32 + tm * 16 + rh * 8 + qrow;
            int rg = row0 + rloc;
            bool v = rg < M;
#pragma unroll
            for (int tn = 0; tn < 8; ++tn) {
                int c = warpN * 64 + tn * 8 + qc;
                float a0 = acc[tm][tn][rh * 2 + 0] + sbias[c];
                float a1 = acc[tm][tn][rh * 2 + 1] + sbias[c + 1];
                if (MODE == 0) {
                    if (v) {
                        float2 q = *(const float2*)(resid + (size_t)rg * 256 + c);
                        a0 += q.x; a1 += q.y;
                    }
                    vsum[tm * 2 + rh] += a0 + a1;
                    vsq[tm * 2 + rh] += a0 * a0 + a1 * a1;
                } else {
                    a0 = fmaxf(a0, 0.f); a1 = fmaxf(a1, 0.f);
                }
                acc[tm][tn][rh * 2 + 0] = a0;
                acc[tm][tn][rh * 2 + 1] = a1;
            }
        }
    }

    if (MODE == 0) {
#pragma unroll
        for (int k = 0; k < 4; ++k) {
            vsum[k] += __shfl_xor_sync(0xFFFFFFFFu, vsum[k], 1);
            vsum[k] += __shfl_xor_sync(0xFFFFFFFFu, vsum[k], 2);
            vsq[k]  += __shfl_xor_sync(0xFFFFFFFFu, vsq[k], 1);
            vsq[k]  += __shfl_xor_sync(0xFFFFFFFFu, vsq[k], 2);
        }
        if ((lane & 3) == 0) {
#pragma unroll
            for (int tm = 0; tm < 2; ++tm)
#pragma unroll
                for (int rh = 0; rh < 2; ++rh) {
                    int rloc = warpM * 32 + tm * 16 + rh * 8 + qrow;
                    atomicAdd(&rsum[rloc], vsum[tm * 2 + rh]);
                    atomicAdd(&rsq[rloc], vsq[tm * 2 + rh]);
                }
        }
        __syncthreads();
    }

#pragma unroll
    for (int tm = 0; tm < 2; ++tm) {
#pragma unroll
        for (int rh = 0; rh < 2; ++rh) {
            int rloc = warpM * 32 + tm * 16 + rh * 8 + qrow;
            int rg = row0 + rloc;
            if (rg >= M) continue;
            float mean = 0.f, inv = 1.f;
            if (MODE == 0) {
                mean = rsum[rloc] * (1.f / 256.f);
                inv = rsqrtf(rsq[rloc] * (1.f / 256.f) - mean * mean + 1e-5f);
            }
#pragma unroll
            for (int tn = 0; tn < 8; ++tn) {
                int c = warpN * 64 + tn * 8 + qc;
                float a0 = acc[tm][tn][rh * 2 + 0];
                float a1 = acc[tm][tn][rh * 2 + 1];
                if (MODE == 0) {
                    a0 = (a0 - mean) * inv * sgam[c] + sbet[c];
                    a1 = (a1 - mean) * inv * sgam[c + 1] + sbet[c + 1];
                    *(float2*)(outf + (size_t)rg * 256 + c) = make_float2(a0, a1);
                    if (outh != nullptr)
                        ((uint32_t*)outh)[((size_t)rg * 256 + c) >> 1] = packh2(a0, a1);
                } else {
                    ((uint32_t*)outh)[((size_t)rg * HF + col0 + c) >> 1] = packh2(a0, a1);
                }
            }
        }
    }
}

// ------------------------------ launch --------------------------------------
extern "C" void kernel_launch(void* const* d_in, const int* in_sizes, int n_in,
                              void* d_out, int out_size) {
    const float* x      = (const float*)d_in[0];
    const int*   ei     = (const int*)d_in[1];
    const float* W_nbr  = (const float*)d_in[2];
    const float* W_root = (const float*)d_in[3];
    const float* b_gnn  = (const float*)d_in[4];
    const float* W1     = (const float*)d_in[5];
    const float* b1     = (const float*)d_in[6];
    const float* W2     = (const float*)d_in[7];
    const float* b2     = (const float*)d_in[8];
    const float* g1     = (const float*)d_in[9];
    const float* be1    = (const float*)d_in[10];
    const float* g2     = (const float*)d_in[11];
    const float* be2    = (const float*)d_in[12];
    float* out = (float*)d_out;

    const int M = in_sizes[0] / HD;
    const int E = in_sizes[1] / 2;

    float* h;
    __half *xh, *agh, *hh, *th, *wnh, *wrh, *w1h, *w2h;
    int *deg, *off, *cur, *srcl;
    cudaGetSymbolAddress((void**)&h, g_h);
    cudaGetSymbolAddress((void**)&xh, g_x_h);
    cudaGetSymbolAddress((void**)&agh, g_ag_h);
    cudaGetSymbolAddress((void**)&hh, g_h_h);
    cudaGetSymbolAddress((void**)&th, g_t_h);
    cudaGetSymbolAddress((void**)&wnh, g_wn_h);
    cudaGetSymbolAddress((void**)&wrh, g_wr_h);
    cudaGetSymbolAddress((void**)&w1h, g_w1_h);
    cudaGetSymbolAddress((void**)&w2h, g_w2_h);
    cudaGetSymbolAddress((void**)&deg, g_deg);
    cudaGetSymbolAddress((void**)&off, g_off);
    cudaGetSymbolAddress((void**)&cur, g_cur);
    cudaGetSymbolAddress((void**)&srcl, g_srcl);

    cudaFuncSetAttribute(gemm_mma<0>, cudaFuncAttributeMaxDynamicSharedMemorySize, SMEM_TOTAL);
    cudaFuncSetAttribute(gemm_mma<1>, cudaFuncAttributeMaxDynamicSharedMemorySize, SMEM_TOTAL);

    int n4 = M * HD / 4;
    conv_kernel<<<(n4 + 255) / 256, 256>>>(x, xh, n4);
    detect_kernel<<<1, 1>>>(ei, 2 * E);

    cudaMemsetAsync(deg, 0, M * sizeof(int));
    hist_kernel<<<(E / 2 + 255) / 256, 256>>>(ei, E, deg);
    scan_kernel<<<1, 1024>>>(deg, off, cur, M);
    fill_kernel<<<(E / 2 + 255) / 256, 256>>>(ei, E, cur, srcl);
    gather_kernel<<<(M + 7) / 8, 256>>>(off, srcl, xh, agh, M);

    ttrans_kernel<<<dim3(HD / 32, HD / 32), dim3(32, 8)>>>(W_nbr, wnh, HD, HD);
    ttrans_kernel<<<dim3(HD / 32, HD / 32), dim3(32, 8)>>>(W_root, wrh, HD, HD);
    ttrans_kernel<<<dim3(HD / 32, HF / 32), dim3(32, 8)>>>(W1, w1h, HD, HF);
    ttrans_kernel<<<dim3(HF / 32, HD / 32), dim3(32, 8)>>>(W2, w2h, HF, HD);

    int gx = (M + 63) / 64;

    // h = LN1(x + agg@Wnbr + x@Wroot + b_gnn), emit fp16 of h
    gemm_mma<0><<<dim3(gx, 1), 256, SMEM_TOTAL>>>(
        agh, wnh, HD, xh, wrh, HD, b_gnn, x, g1, be1, h, hh, M);

    // t = relu(h@W1 + b1) (fp16 only)
    gemm_mma<1><<<dim3(gx, 2), 256, SMEM_TOTAL>>>(
        hh, w1h, HD, nullptr, nullptr, 0,
        b1, nullptr, nullptr, nullptr, nullptr, th, M);

    // out = LN2(h + t@W2 + b2)
    gemm_mma<0><<<dim3(gx, 1), 256, SMEM_TOTAL>>>(
        th, w2h, HF, nullptr, nullptr, 0,
        b2, h, g2, be2, out, nullptr, M);
}

// round 8
// speedup vs baseline: 3.9194x; 1.2165x over previous
#include <cuda_runtime.h>
#include <cuda_fp16.h>
#include <cstdint>

#define HD 256
#define HF 512
#define NMAX 50000
#define EMAX 800000
#define SCAN_BLK 512

// ------------------------- scratch (device globals) ------------------------
__device__ float g_h[(size_t)NMAX * HD];
__device__ __half g_x_h[(size_t)NMAX * HD];
__device__ __half g_ag_h[(size_t)NMAX * HD];
__device__ __half g_h_h[(size_t)NMAX * HD];
__device__ __half g_t_h[(size_t)NMAX * HF];
__device__ __half g_wn_h[HD * HD];
__device__ __half g_wr_h[HD * HD];
__device__ __half g_w1_h[HD * HF];
__device__ __half g_w2_h[HD * HF];
__device__ int g_deg[NMAX];
__device__ int g_off[NMAX + 1];
__device__ int g_cur[NMAX];
__device__ int g_srcl[EMAX];
__device__ int g_bsum[(NMAX + SCAN_BLK - 1) / SCAN_BLK];
__device__ int g_is64;

// ----------------------------- helpers -------------------------------------
__device__ __forceinline__ uint32_t smem_u32(const void* p) {
    uint32_t a;
    asm("{ .reg .u64 t; cvta.to.shared.u64 t, %1; cvt.u32.u64 %0, t; }" : "=r"(a) : "l"(p));
    return a;
}
__device__ __forceinline__ void ldsm_x4(uint32_t* r, uint32_t addr) {
    asm volatile("ldmatrix.sync.aligned.m8n8.x4.shared.b16 {%0,%1,%2,%3}, [%4];"
                 : "=r"(r[0]), "=r"(r[1]), "=r"(r[2]), "=r"(r[3]) : "r"(addr));
}
__device__ __forceinline__ void mma_f16(float* d, const uint32_t* a, const uint32_t* b) {
    asm volatile(
        "mma.sync.aligned.m16n8k16.row.col.f32.f16.f16.f32 "
        "{%0,%1,%2,%3}, {%4,%5,%6,%7}, {%8,%9}, {%0,%1,%2,%3};"
        : "+f"(d[0]), "+f"(d[1]), "+f"(d[2]), "+f"(d[3])
        : "r"(a[0]), "r"(a[1]), "r"(a[2]), "r"(a[3]), "r"(b[0]), "r"(b[1]));
}
__device__ __forceinline__ void cp_async16(uint32_t dst, const void* src, int szr) {
    asm volatile("cp.async.cg.shared.global [%0], [%1], 16, %2;"
                 :: "r"(dst), "l"(src), "r"(szr) : "memory");
}
#define CP_COMMIT() asm volatile("cp.async.commit_group;" ::: "memory")
#define CP_WAIT2()  asm volatile("cp.async.wait_group 2;" ::: "memory")
#define CP_WAIT0()  asm volatile("cp.async.wait_group 0;" ::: "memory")

__device__ __forceinline__ uint32_t packh2(float a, float b) {
    __half2 h = __float22half2_rn(make_float2(a, b));
    return *(uint32_t*)&h;
}

// --------------------------- small kernels ---------------------------------
__global__ void detect_kernel(const int* __restrict__ ei, int twoE) {
    int nz = 0;
    int lim = twoE * 2;
    if (lim > 256) lim = 256;
    for (int i = 1; i < lim; i += 2) nz |= ei[i];
    g_is64 = (nz == 0) ? 1 : 0;
}

__global__ void hist_kernel(const int* __restrict__ ei, int E, int* __restrict__ deg) {
    int t = blockIdx.x * blockDim.x + threadIdx.x;
    if (g_is64) {
        int e0 = t * 2;
        if (e0 >= E) return;
        if (e0 + 2 <= E) {
            int4 d = *(const int4*)(ei + 2 * (E + e0));
            atomicAdd(&deg[d.x], 1);
            atomicAdd(&deg[d.z], 1);
        } else {
            atomicAdd(&deg[ei[2 * (E + e0)]], 1);
        }
    } else {
        int e0 = t * 4;
        if (e0 >= E) return;
        if (e0 + 4 <= E) {
            int4 d = *(const int4*)(ei + E + e0);
            atomicAdd(&deg[d.x], 1);
            atomicAdd(&deg[d.y], 1);
            atomicAdd(&deg[d.z], 1);
            atomicAdd(&deg[d.w], 1);
        } else {
            for (int e = e0; e < E; ++e) atomicAdd(&deg[ei[E + e]], 1);
        }
    }
}

// ---- parallel 3-phase scan ----
// phase 1: per-block exclusive scan (1 elem/thread), block totals to bsum
__global__ void block_scan_kernel(const int* __restrict__ deg, int* __restrict__ off,
                                  int* __restrict__ bsum, int M) {
    __shared__ int wsum[SCAN_BLK / 32];
    int t = threadIdx.x;
    int i = blockIdx.x * SCAN_BLK + t;
    int lane = t & 31, wid = t >> 5;
    int v = (i < M) ? deg[i] : 0;
    int s = v;
#pragma unroll
    for (int o = 1; o < 32; o <<= 1) {
        int u = __shfl_up_sync(0xFFFFFFFFu, s, o);
        if (lane >= o) s += u;
    }
    if (lane == 31) wsum[wid] = s;
    __syncthreads();
    if (wid == 0) {
        int w = (lane < SCAN_BLK / 32) ? wsum[lane] : 0;
#pragma unroll
        for (int o = 1; o < SCAN_BLK / 32; o <<= 1) {
            int u = __shfl_up_sync(0xFFFFFFFFu, w, o);
            if (lane >= o) w += u;
        }
        if (lane < SCAN_BLK / 32) wsum[lane] = w;   // inclusive warp totals
    }
    __syncthreads();
    int excl = s - v + (wid ? wsum[wid - 1] : 0);
    if (i < M) off[i] = excl;                        // block-relative
    if (t == SCAN_BLK - 1) bsum[blockIdx.x] = excl + v;
}

// phase 2: scan block totals (nB <= 128), write grand total to off[M]
__global__ void bscan_kernel(int* __restrict__ bsum, int* __restrict__ offM, int nB) {
    __shared__ int ws[4];
    int t = threadIdx.x;        // 128 threads
    int lane = t & 31, wid = t >> 5;
    int v = (t < nB) ? bsum[t] : 0;
    int s = v;
#pragma unroll
    for (int o = 1; o < 32; o <<= 1) {
        int u = __shfl_up_sync(0xFFFFFFFFu, s, o);
        if (lane >= o) s += u;
    }
    if (lane == 31) ws[wid] = s;
    __syncthreads();
    if (t == 0) {
        int r = 0;
#pragma unroll
        for (int i = 0; i < 4; ++i) { int x = ws[i]; ws[i] = r; r += x; }
        *offM = r;
    }
    __syncthreads();
    int excl = s - v + ws[wid];
    if (t < nB) bsum[t] = excl;
}

// phase 3: add block prefix, mirror into cur
__global__ void add_off_kernel(int* __restrict__ off, int* __restrict__ cur,
                               const int* __restrict__ bsum, int M) {
    int i = blockIdx.x * SCAN_BLK + threadIdx.x;
    if (i < M) {
        int v = off[i] + bsum[blockIdx.x];
        off[i] = v;
        cur[i] = v;
    }
}

__global__ void fill_kernel(const int* __restrict__ ei, int E,
                            int* __restrict__ cur, int* __restrict__ srcl) {
    int t = blockIdx.x * blockDim.x + threadIdx.x;
    if (g_is64) {
        int e0 = t * 2;
        if (e0 >= E) return;
        if (e0 + 2 <= E) {
            int4 s = *(const int4*)(ei + 2 * e0);
            int4 d = *(const int4*)(ei + 2 * (E + e0));
            srcl[atomicAdd(&cur[d.x], 1)] = s.x;
            srcl[atomicAdd(&cur[d.z], 1)] = s.z;
        } else {
            srcl[atomicAdd(&cur[ei[2 * (E + e0)]], 1)] = ei[2 * e0];
        }
    } else {
        int e0 = t * 4;
        if (e0 >= E) return;
        if (e0 + 4 <= E) {
            int4 s = *(const int4*)(ei + e0);
            int4 d = *(const int4*)(ei + E + e0);
            srcl[atomicAdd(&cur[d.x], 1)] = s.x;
            srcl[atomicAdd(&cur[d.y], 1)] = s.y;
            srcl[atomicAdd(&cur[d.z], 1)] = s.z;
            srcl[atomicAdd(&cur[d.w], 1)] = s.w;
        } else {
            for (int e = e0; e < E; ++e)
                srcl[atomicAdd(&cur[ei[E + e]], 1)] = ei[e];
        }
    }
}

// gather: one warp per node; unroll-8 neighbor batches; emit fp16 agg
__global__ void __launch_bounds__(256)
gather_kernel(const int* __restrict__ off, const int* __restrict__ srcl,
              const __half* __restrict__ xh, __half* __restrict__ agh, int M) {
    int node = blockIdx.x * 8 + (threadIdx.x >> 5);
    int lane = threadIdx.x & 31;
    if (node >= M) return;
    int j0 = off[node], j1 = off[node + 1];

    float acc[8];
#pragma unroll
    for (int k = 0; k < 8; ++k) acc[k] = 0.f;

    const uint4* xb = (const uint4*)xh;
    int j = j0;
    for (; j + 8 <= j1; j += 8) {
        int srcs[8];
#pragma unroll
        for (int u = 0; u < 8; ++u) srcs[u] = srcl[j + u];
        uint4 v[8];
#pragma unroll
        for (int u = 0; u < 8; ++u) v[u] = xb[(size_t)srcs[u] * 32 + lane];
#pragma unroll
        for (int u = 0; u < 8; ++u) {
            float2 f0 = __half22float2(*(const __half2*)&v[u].x);
            float2 f1 = __half22float2(*(const __half2*)&v[u].y);
            float2 f2 = __half22float2(*(const __half2*)&v[u].z);
            float2 f3 = __half22float2(*(const __half2*)&v[u].w);
            acc[0] += f0.x; acc[1] += f0.y; acc[2] += f1.x; acc[3] += f1.y;
            acc[4] += f2.x; acc[5] += f2.y; acc[6] += f3.x; acc[7] += f3.y;
        }
    }
    for (; j < j1; ++j) {
        uint4 v = xb[(size_t)srcl[j] * 32 + lane];
        float2 f0 = __half22float2(*(const __half2*)&v.x);
        float2 f1 = __half22float2(*(const __half2*)&v.y);
        float2 f2 = __half22float2(*(const __half2*)&v.z);
        float2 f3 = __half22float2(*(const __half2*)&v.w);
        acc[0] += f0.x; acc[1] += f0.y; acc[2] += f1.x; acc[3] += f1.y;
        acc[4] += f2.x; acc[5] += f2.y; acc[6] += f3.x; acc[7] += f3.y;
    }

    uint32_t hi[4];
#pragma unroll
    for (int k = 0; k < 4; ++k) hi[k] = packh2(acc[2 * k], acc[2 * k + 1]);
    ((uint4*)agh)[(size_t)node * 32 + lane] = make_uint4(hi[0], hi[1], hi[2], hi[3]);
}

__global__ void conv_kernel(const float* __restrict__ in,
                            __half* __restrict__ oh, int n4) {
    int i = blockIdx.x * blockDim.x + threadIdx.x;
    if (i >= n4) return;
    float4 v = ((const float4*)in)[i];
    ((uint2*)oh)[i] = make_uint2(packh2(v.x, v.y), packh2(v.z, v.w));
}

// tiled transpose: W [K,N] fp32 -> out [N,K] fp16, coalesced both sides
__global__ void ttrans_kernel(const float* __restrict__ W,
                              __half* __restrict__ out, int K, int N) {
    __shared__ float tile[32][33];
    int k0 = blockIdx.x * 32;
    int n0 = blockIdx.y * 32;
    int tx = threadIdx.x, ty = threadIdx.y;   // 32 x 8
#pragma unroll
    for (int i = 0; i < 4; ++i)
        tile[ty + i * 8][tx] = W[(size_t)(k0 + ty + i * 8) * N + n0 + tx];
    __syncthreads();
#pragma unroll
    for (int i = 0; i < 4; ++i)
        out[(size_t)(n0 + ty + i * 8) * K + k0 + tx] =
            __float2half_rn(tile[tx][ty + i * 8]);
}

// ----------------------- fp16 single-term mma.sync GEMM --------------------
// BM=64, BN=256, BK=32, 256 threads, 4-stage cp.async pipeline, 2 CTAs/SM.
#define STAGE_BYTES 25600
#define NSTAGE 4
#define SMEM_TOTAL (NSTAGE * STAGE_BYTES)

__device__ __forceinline__ void load_stage(
    uint32_t sa, int tid, int row0, int col0,
    const __half* A, const __half* B, int K, int kc, int M) {
    {
        int r = tid >> 2, c = tid & 3;
        int row = row0 + r;
        int szr = (row < M) ? 16 : 0;
        size_t roff = (row < M) ? (size_t)row : 0;
        cp_async16(sa + r * 80 + c * 16, A + roff * K + kc + c * 8, szr);
    }
    uint32_t sb = sa + 5120;
#pragma unroll
    for (int j = 0; j < 4; ++j) {
        int id = tid + j * 256;
        int r = id >> 2, c = id & 3;
        cp_async16(sb + r * 80 + c * 16, B + (size_t)(col0 + r) * K + kc + c * 8, 16);
    }
}

template <int MODE>
__global__ void __launch_bounds__(256, 2)
gemm_mma(const __half* __restrict__ A0, const __half* __restrict__ B0, int K0,
         const __half* __restrict__ A1, const __half* __restrict__ B1, int K1,
         const float* __restrict__ bias, const float* __restrict__ resid,
         const float* __restrict__ gamma, const float* __restrict__ beta,
         float* __restrict__ outf, __half* __restrict__ outh, int M) {
    extern __shared__ char smem[];
    const uint32_t sb0 = smem_u32(smem);
    const int tid = threadIdx.x;
    const int lane = tid & 31;
    const int warp = tid >> 5;
    const int warpM = warp >> 2;
    const int warpN = warp & 3;
    const int row0 = blockIdx.x * 64;
    const int col0 = blockIdx.y * 256;

    float acc[2][8][4];
#pragma unroll
    for (int i = 0; i < 2; ++i)
#pragma unroll
        for (int j = 0; j < 8; ++j)
#pragma unroll
            for (int k = 0; k < 4; ++k) acc[i][j][k] = 0.f;

    const int S = (K0 + K1) >> 5;

    const uint32_t aoff = (uint32_t)((warpM * 32 + (lane & 7) + ((lane >> 3) & 1) * 8) * 80
                                     + (lane >> 4) * 16);
    const uint32_t boff4 = (uint32_t)((warpN * 64 + (lane & 7) + (lane >> 4) * 8) * 80
                                      + ((lane >> 3) & 1) * 16);

#define RESOLVE(IT, AH, BH, KK, KC)                             \
    { int kt = (IT) * 32;                                       \
      if (kt < K0) { AH = A0; BH = B0; KK = K0; KC = kt; }      \
      else         { AH = A1; BH = B1; KK = K1; KC = kt - K0; } }

#pragma unroll
    for (int p = 0; p < NSTAGE - 1; ++p) {
        if (p < S) {
            const __half *Ah, *Bh; int KK, KC;
            RESOLVE(p, Ah, Bh, KK, KC);
            load_stage(sb0 + p * STAGE_BYTES, tid, row0, col0, Ah, Bh, KK, KC, M);
        }
        CP_COMMIT();
    }

    int stage = 0;
    for (int it = 0; it < S; ++it) {
        CP_WAIT2();
        __syncthreads();
        if (it + NSTAGE - 1 < S) {
            int s2 = stage + NSTAGE - 1; if (s2 >= NSTAGE) s2 -= NSTAGE;
            const __half *Ah, *Bh; int KK, KC;
            RESOLVE(it + NSTAGE - 1, Ah, Bh, KK, KC);
            load_stage(sb0 + s2 * STAGE_BYTES, tid, row0, col0, Ah, Bh, KK, KC, M);
        }
        CP_COMMIT();

        const uint32_t sa = sb0 + stage * STAGE_BYTES;
        const uint32_t sbB = sa + 5120;
#pragma unroll
        for (int ks = 0; ks < 2; ++ks) {
            uint32_t ah[2][4];
#pragma unroll
            for (int tm = 0; tm < 2; ++tm)
                ldsm_x4(ah[tm], sa + aoff + tm * 1280 + ks * 32);
#pragma unroll
            for (int tnp = 0; tnp < 4; ++tnp) {
                uint32_t bh[4];
                ldsm_x4(bh, sbB + boff4 + tnp * 1280 + ks * 32);
#pragma unroll
                for (int tm = 0; tm < 2; ++tm) {
                    mma_f16(acc[tm][2 * tnp + 0], ah[tm], bh);
                    mma_f16(acc[tm][2 * tnp + 1], ah[tm], bh + 2);
                }
            }
        }
        ++stage; if (stage == NSTAGE) stage = 0;
    }

    CP_WAIT0();
    __syncthreads();

    // ---------------------------- epilogue ---------------------------------
    float* rsum  = (float*)smem;
    float* rsq   = rsum + 64;
    float* sbias = rsq + 64;
    float* sgam  = sbias + 256;
    float* sbet  = sgam + 256;
    if (MODE == 0 && tid < 64) { rsum[tid] = 0.f; rsq[tid] = 0.f; }
    sbias[tid] = bias[col0 + tid];
    if (MODE == 0) { sgam[tid] = gamma[tid]; sbet[tid] = beta[tid]; }
    __syncthreads();

    const int qrow = lane >> 2;
    const int qc = (lane & 3) * 2;

    float vsum[4], vsq[4];
#pragma unroll
    for (int k = 0; k < 4; ++k) { vsum[k] = 0.f; vsq[k] = 0.f; }

#pragma unroll
    for (int tm = 0; tm < 2; ++tm) {
#pragma unroll
        for (int rh = 0; rh < 2; ++rh) {
            int rloc = warpM * 32 + tm * 16 + rh * 8 + qrow;
            int rg = row0 + rloc;
            bool v = rg < M;
#pragma unroll
            for (int tn = 0; tn < 8; ++tn) {
                int c = warpN * 64 + tn * 8 + qc;
                float a0 = acc[tm][tn][rh * 2 + 0] + sbias[c];
                float a1 = acc[tm][tn][rh * 2 + 1] + sbias[c + 1];
                if (MODE == 0) {
                    if (v) {
                        float2 q = *(const float2*)(resid + (size_t)rg * 256 + c);
                        a0 += q.x; a1 += q.y;
                    }
                    vsum[tm * 2 + rh] += a0 + a1;
                    vsq[tm * 2 + rh] += a0 * a0 + a1 * a1;
                } else {
                    a0 = fmaxf(a0, 0.f); a1 = fmaxf(a1, 0.f);
                }
                acc[tm][tn][rh * 2 + 0] = a0;
                acc[tm][tn][rh * 2 + 1] = a1;
            }
        }
    }

    if (MODE == 0) {
#pragma unroll
        for (int k = 0; k < 4; ++k) {
            vsum[k] += __shfl_xor_sync(0xFFFFFFFFu, vsum[k], 1);
            vsum[k] += __shfl_xor_sync(0xFFFFFFFFu, vsum[k], 2);
            vsq[k]  += __shfl_xor_sync(0xFFFFFFFFu, vsq[k], 1);
            vsq[k]  += __shfl_xor_sync(0xFFFFFFFFu, vsq[k], 2);
        }
        if ((lane & 3) == 0) {
#pragma unroll
            for (int tm = 0; tm < 2; ++tm)
#pragma unroll
                for (int rh = 0; rh < 2; ++rh) {
                    int rloc = warpM * 32 + tm * 16 + rh * 8 + qrow;
                    atomicAdd(&rsum[rloc], vsum[tm * 2 + rh]);
                    atomicAdd(&rsq[rloc], vsq[tm * 2 + rh]);
                }
        }
        __syncthreads();
    }

#pragma unroll
    for (int tm = 0; tm < 2; ++tm) {
#pragma unroll
        for (int rh = 0; rh < 2; ++rh) {
            int rloc = warpM * 32 + tm * 16 + rh * 8 + qrow;
            int rg = row0 + rloc;
            if (rg >= M) continue;
            float mean = 0.f, inv = 1.f;
            if (MODE == 0) {
                mean = rsum[rloc] * (1.f / 256.f);
                inv = rsqrtf(rsq[rloc] * (1.f / 256.f) - mean * mean + 1e-5f);
            }
#pragma unroll
            for (int tn = 0; tn < 8; ++tn) {
                int c = warpN * 64 + tn * 8 + qc;
                float a0 = acc[tm][tn][rh * 2 + 0];
                float a1 = acc[tm][tn][rh * 2 + 1];
                if (MODE == 0) {
                    a0 = (a0 - mean) * inv * sgam[c] + sbet[c];
                    a1 = (a1 - mean) * inv * sgam[c + 1] + sbet[c + 1];
                    *(float2*)(outf + (size_t)rg * 256 + c) = make_float2(a0, a1);
                    if (outh != nullptr)
                        ((uint32_t*)outh)[((size_t)rg * 256 + c) >> 1] = packh2(a0, a1);
                } else {
                    ((uint32_t*)outh)[((size_t)rg * HF + col0 + c) >> 1] = packh2(a0, a1);
                }
            }
        }
    }
}

// ------------------------------ launch --------------------------------------
extern "C" void kernel_launch(void* const* d_in, const int* in_sizes, int n_in,
                              void* d_out, int out_size) {
    const float* x      = (const float*)d_in[0];
    const int*   ei     = (const int*)d_in[1];
    const float* W_nbr  = (const float*)d_in[2];
    const float* W_root = (const float*)d_in[3];
    const float* b_gnn  = (const float*)d_in[4];
    const float* W1     = (const float*)d_in[5];
    const float* b1     = (const float*)d_in[6];
    const float* W2     = (const float*)d_in[7];
    const float* b2     = (const float*)d_in[8];
    const float* g1     = (const float*)d_in[9];
    const float* be1    = (const float*)d_in[10];
    const float* g2     = (const float*)d_in[11];
    const float* be2    = (const float*)d_in[12];
    float* out = (float*)d_out;

    const int M = in_sizes[0] / HD;
    const int E = in_sizes[1] / 2;

    float* h;
    __half *xh, *agh, *hh, *th, *wnh, *wrh, *w1h, *w2h;
    int *deg, *off, *cur, *srcl, *bsum;
    cudaGetSymbolAddress((void**)&h, g_h);
    cudaGetSymbolAddress((void**)&xh, g_x_h);
    cudaGetSymbolAddress((void**)&agh, g_ag_h);
    cudaGetSymbolAddress((void**)&hh, g_h_h);
    cudaGetSymbolAddress((void**)&th, g_t_h);
    cudaGetSymbolAddress((void**)&wnh, g_wn_h);
    cudaGetSymbolAddress((void**)&wrh, g_wr_h);
    cudaGetSymbolAddress((void**)&w1h, g_w1_h);
    cudaGetSymbolAddress((void**)&w2h, g_w2_h);
    cudaGetSymbolAddress((void**)&deg, g_deg);
    cudaGetSymbolAddress((void**)&off, g_off);
    cudaGetSymbolAddress((void**)&cur, g_cur);
    cudaGetSymbolAddress((void**)&srcl, g_srcl);
    cudaGetSymbolAddress((void**)&bsum, g_bsum);

    cudaFuncSetAttribute(gemm_mma<0>, cudaFuncAttributeMaxDynamicSharedMemorySize, SMEM_TOTAL);
    cudaFuncSetAttribute(gemm_mma<1>, cudaFuncAttributeMaxDynamicSharedMemorySize, SMEM_TOTAL);

    int n4 = M * HD / 4;
    conv_kernel<<<(n4 + 255) / 256, 256>>>(x, xh, n4);
    detect_kernel<<<1, 1>>>(ei, 2 * E);

    cudaMemsetAsync(deg, 0, M * sizeof(int));
    hist_kernel<<<(E / 2 + 255) / 256, 256>>>(ei, E, deg);

    int nB = (M + SCAN_BLK - 1) / SCAN_BLK;
    block_scan_kernel<<<nB, SCAN_BLK>>>(deg, off, bsum, M);
    bscan_kernel<<<1, 128>>>(bsum, off + M, nB);
    add_off_kernel<<<nB, SCAN_BLK>>>(off, cur, bsum, M);

    fill_kernel<<<(E / 2 + 255) / 256, 256>>>(ei, E, cur, srcl);
    gather_kernel<<<(M + 7) / 8, 256>>>(off, srcl, xh, agh, M);

    ttrans_kernel<<<dim3(HD / 32, HD / 32), dim3(32, 8)>>>(W_nbr, wnh, HD, HD);
    ttrans_kernel<<<dim3(HD / 32, HD / 32), dim3(32, 8)>>>(W_root, wrh, HD, HD);
    ttrans_kernel<<<dim3(HD / 32, HF / 32), dim3(32, 8)>>>(W1, w1h, HD, HF);
    ttrans_kernel<<<dim3(HF / 32, HD / 32), dim3(32, 8)>>>(W2, w2h, HF, HD);

    int gx = (M + 63) / 64;

    // h = LN1(x + agg@Wnbr + x@Wroot + b_gnn), emit fp16 of h
    gemm_mma<0><<<dim3(gx, 1), 256, SMEM_TOTAL>>>(
        agh, wnh, HD, xh, wrh, HD, b_gnn, x, g1, be1, h, hh, M);

    // t = relu(h@W1 + b1) (fp16 only)
    gemm_mma<1><<<dim3(gx, 2), 256, SMEM_TOTAL>>>(
        hh, w1h, HD, nullptr, nullptr, 0,
        b1, nullptr, nullptr, nullptr, nullptr, th, M);

    // out = LN2(h + t@W2 + b2)
    gemm_mma<0><<<dim3(gx, 1), 256, SMEM_TOTAL>>>(
        th, w2h, HF, nullptr, nullptr, 0,
        b2, h, g2, be2, out, nullptr, M);
}